// round 6
// baseline (speedup 1.0000x reference)
#include <cuda_runtime.h>
#include <math.h>

// ---------------------------------------------------------------------------
// Static scratch (allocation-free per harness rules)
// ---------------------------------------------------------------------------
#define N2MAX 1536
#define G2MAX (8*N2MAX)
#define U1MAX 15872
#define G1MAX (8*U1MAX)
#define U0MAX 160256

__device__ float g_acc2[(N2MAX+1)*128];
__device__ float g_tg2[(size_t)G2MAX*128];
__device__ float g_accg2[((size_t)G2MAX+1)*128];
__device__ float g_x1[(size_t)U1MAX*128];
__device__ float g_acc1[((size_t)U1MAX+1)*128];
__device__ float g_t1[(size_t)G1MAX*64];
__device__ float g_accg1[((size_t)G1MAX+1)*64];
__device__ float g_x0[(size_t)U0MAX*64];
__device__ float g_acc0[((size_t)U0MAX+1)*128];
__device__ float g_stats[256];

#define PAD 20   // smem row stride (words): conflict-free mma fragment LDS

__device__ __forceinline__ unsigned f2tf32(float f) {
    unsigned r;
    asm("cvt.rna.tf32.f32 %0, %1;" : "=r"(r) : "f"(f));
    return r;
}

__device__ __forceinline__ void mma_tf32(float& c0, float& c1, float& c2, float& c3,
                                         unsigned a0, unsigned a1, unsigned a2, unsigned a3,
                                         unsigned b0, unsigned b1)
{
    asm volatile("mma.sync.aligned.m16n8k8.row.col.f32.tf32.tf32.f32 "
                 "{%0,%1,%2,%3},{%4,%5,%6,%7},{%8,%9},{%0,%1,%2,%3};"
                 : "+f"(c0), "+f"(c1), "+f"(c2), "+f"(c3)
                 : "r"(a0), "r"(a1), "r"(a2), "r"(a3), "r"(b0), "r"(b1));
}

__device__ __forceinline__ void red_add_v2(float* p, float a, float b) {
    asm volatile("red.global.add.v2.f32 [%0], {%1,%2};"
                 :: "l"(p), "f"(a), "f"(b) : "memory");
}

// ---------------------------------------------------------------------------
// Warp MMA step over one 128 x TN smem tile slice (k = 16).
// Warps: 4(m) x 2(n). Warp tile: 32 x TN/2. NI = TN/16 n8-tiles per warp.
// ---------------------------------------------------------------------------
template<int NI>
__device__ __forceinline__ void mma_step(const unsigned (*As)[PAD],
                                         const unsigned (*Bs)[PAD],
                                         int wm, int wn, int lane,
                                         float (&c)[2][NI][4])
{
    const int qr = lane >> 2;
    const int qc = lane & 3;
    #pragma unroll
    for (int kt = 0; kt < 2; kt++) {
        const int kb = kt * 8;
        unsigned a[2][4];
        #pragma unroll
        for (int mi = 0; mi < 2; mi++) {
            const int rb = wm + mi * 16 + qr;
            a[mi][0] = As[rb    ][kb + qc];
            a[mi][1] = As[rb + 8][kb + qc];
            a[mi][2] = As[rb    ][kb + qc + 4];
            a[mi][3] = As[rb + 8][kb + qc + 4];
        }
        unsigned b[NI][2];
        #pragma unroll
        for (int ni = 0; ni < NI; ni++) {
            const int nb = wn + ni * 8 + qr;
            b[ni][0] = Bs[nb][kb + qc];
            b[ni][1] = Bs[nb][kb + qc + 4];
        }
        #pragma unroll
        for (int mi = 0; mi < 2; mi++)
            #pragma unroll
            for (int ni = 0; ni < NI; ni++)
                mma_tf32(c[mi][ni][0], c[mi][ni][1], c[mi][ni][2], c[mi][ni][3],
                         a[mi][0], a[mi][1], a[mi][2], a[mi][3], b[ni][0], b[ni][1]);
    }
}

// ---------------------------------------------------------------------------
// Output-stationary sparse conv (NO atomics): one block per 128-row output
// tile, 27-tap loop with register-resident accumulator. Exploits that om[t]
// is sorted ascending per tap (reference builds it via np.nonzero).
// Y[o] = sum_t X[im(t, e(o))] @ W[tap(t)]   (+ center tap identity)
// Every output row is written exactly once with plain stores.
// ---------------------------------------------------------------------------
template<int TN>
__global__ __launch_bounds__(256, 2) void conv_gather_t(
    const float* __restrict__ X, const float* __restrict__ W27,
    float* __restrict__ Y, const int* __restrict__ maps,
    int Mpad, int n, int cin)
{
    constexpr int cout = TN;
    constexpr int NI = TN / 16;
    constexpr int BL = TN / 16;
    constexpr int KS = 256 / TN;

    __shared__ unsigned As[2][128][PAD];
    __shared__ unsigned Bs[2][TN][PAD];
    __shared__ int rowsrc[128];
    __shared__ int smom[128];
    __shared__ int smim[128];
    __shared__ int seg[26][2];

    const int o0  = blockIdx.x * 128;
    const int tid = threadIdx.x;

    // segment bounds per tap: lower_bound(om, o0) / lower_bound(om, min(o0+128,n))
    if (tid < 52) {
        const int t = tid >> 1, w = tid & 1;
        const int* om = maps + (size_t)(26 + t) * Mpad;
        const int hi128 = (o0 + 128 < n) ? o0 + 128 : n;
        const int target = w ? hi128 : o0;
        int lo = 0, hi = Mpad;
        while (lo < hi) {
            int mid = (lo + hi) >> 1;
            if (om[mid] < target) lo = mid + 1; else hi = mid;
        }
        seg[t][w] = lo;
    }
    __syncthreads();

    const int lane = tid & 31;
    const int warp = tid >> 5;
    const int wm = (warp & 3) * 32;
    const int wn = (warp >> 2) * (TN / 2);

    const int am0 = tid >> 2, am1 = am0 + 64;
    const int aq  = (tid & 3) * 4;
    const int bn  = tid & (TN - 1);
    const int bk0 = tid / TN;

    float c[2][NI][4];
    #pragma unroll
    for (int mi = 0; mi < 2; mi++)
        #pragma unroll
        for (int ni = 0; ni < NI; ni++)
            #pragma unroll
            for (int j = 0; j < 4; j++) c[mi][ni][j] = 0.f;

    for (int t = 0; t < 27; t++) {
        // ---- build rowsrc for this tap ----
        if (t < 26) {
            const int lb = seg[t][0], ub = seg[t][1];
            const int count = ub - lb;
            if (count == 0) continue;            // uniform (seg in smem)
            const int* om = maps + (size_t)(26 + t) * Mpad;
            const int* im = maps + (size_t)t * Mpad;
            for (int e = tid; e < count; e += 256) {
                smom[e] = om[lb + e];
                smim[e] = im[lb + e];
            }
            __syncthreads();
            if (tid < 128) {
                const int target = o0 + tid;
                int lo = 0, hi = count;
                while (lo < hi) {
                    int mid = (lo + hi) >> 1;
                    if (smom[mid] < target) lo = mid + 1; else hi = mid;
                }
                rowsrc[tid] = (lo < count && smom[lo] == target) ? smim[lo] : -1;
            }
            __syncthreads();
        } else {
            if (tid < 128) rowsrc[tid] = (o0 + tid < n) ? o0 + tid : -1;
            __syncthreads();
        }

        const int tap = (t == 26) ? 13 : ((t < 13) ? t : t + 1);
        const float* W = W27 + (size_t)tap * cin * cout;
        const int g0 = rowsrc[am0], g1 = rowsrc[am1];

        // ---- double-buffered GEMM over cin for this tap ----
        float4 av0, av1; float bv[BL];
        av0 = (g0 >= 0) ? *(const float4*)(X + (size_t)g0 * cin + aq) : make_float4(0,0,0,0);
        av1 = (g1 >= 0) ? *(const float4*)(X + (size_t)g1 * cin + aq) : make_float4(0,0,0,0);
        #pragma unroll
        for (int l = 0; l < BL; l++)
            bv[l] = W[(size_t)(bk0 + l * KS) * cout + bn];
        As[0][am0][aq+0] = f2tf32(av0.x); As[0][am0][aq+1] = f2tf32(av0.y);
        As[0][am0][aq+2] = f2tf32(av0.z); As[0][am0][aq+3] = f2tf32(av0.w);
        As[0][am1][aq+0] = f2tf32(av1.x); As[0][am1][aq+1] = f2tf32(av1.y);
        As[0][am1][aq+2] = f2tf32(av1.z); As[0][am1][aq+3] = f2tf32(av1.w);
        #pragma unroll
        for (int l = 0; l < BL; l++) Bs[0][bn][bk0 + l * KS] = f2tf32(bv[l]);
        __syncthreads();

        int buf = 0;
        for (int k0 = 0;; k0 += 16) {
            const bool more = (k0 + 16 < cin);
            if (more) {
                const int kn = k0 + 16;
                av0 = (g0 >= 0) ? *(const float4*)(X + (size_t)g0 * cin + kn + aq) : make_float4(0,0,0,0);
                av1 = (g1 >= 0) ? *(const float4*)(X + (size_t)g1 * cin + kn + aq) : make_float4(0,0,0,0);
                #pragma unroll
                for (int l = 0; l < BL; l++)
                    bv[l] = W[(size_t)(kn + bk0 + l * KS) * cout + bn];
            }
            mma_step<NI>(As[buf], Bs[buf], wm, wn, lane, c);
            if (!more) break;
            const int nb2 = buf ^ 1;
            As[nb2][am0][aq+0] = f2tf32(av0.x); As[nb2][am0][aq+1] = f2tf32(av0.y);
            As[nb2][am0][aq+2] = f2tf32(av0.z); As[nb2][am0][aq+3] = f2tf32(av0.w);
            As[nb2][am1][aq+0] = f2tf32(av1.x); As[nb2][am1][aq+1] = f2tf32(av1.y);
            As[nb2][am1][aq+2] = f2tf32(av1.z); As[nb2][am1][aq+3] = f2tf32(av1.w);
            #pragma unroll
            for (int l = 0; l < BL; l++) Bs[nb2][bn][bk0 + l * KS] = f2tf32(bv[l]);
            __syncthreads();
            buf = nb2;
        }
        __syncthreads();   // protect rowsrc/smom rebuild next tap
    }

    // ---- epilogue: single plain store per output element ----
    const int qr = lane >> 2, qc = lane & 3;
    #pragma unroll
    for (int mi = 0; mi < 2; mi++) {
        #pragma unroll
        for (int half = 0; half < 2; half++) {
            const int r = o0 + wm + mi * 16 + qr + half * 8;
            if (r >= n) continue;
            float* yp = Y + (size_t)r * cout + wn + qc * 2;
            #pragma unroll
            for (int ni = 0; ni < NI; ni++)
                *(float2*)(yp + ni * 8) = make_float2(c[mi][ni][half*2], c[mi][ni][half*2+1]);
        }
    }
}

// ---------------------------------------------------------------------------
// Scatter-style tap conv (tf32 MMA + RED) for small levels.
// grid = (ceil(n/128), 27)
// ---------------------------------------------------------------------------
template<int TN>
__global__ __launch_bounds__(256, 2) void conv_taps_t(
    const float* __restrict__ X, const float* __restrict__ W27,
    float* __restrict__ C, const int* __restrict__ maps,
    int Mpad, int n, int cin)
{
    constexpr int cout = TN;
    constexpr int NI = TN / 16;
    constexpr int BL = TN / 16;
    constexpr int KS = 256 / TN;

    __shared__ unsigned As[2][128][PAD];
    __shared__ unsigned Bs[2][TN][PAD];
    __shared__ int gidx[128], sidx[128];

    const int z    = blockIdx.y;
    const int Mz   = (z == 26) ? n : Mpad;
    const int row0 = blockIdx.x * 128;
    if (row0 >= Mz) return;

    const int tap  = (z == 26) ? 13 : ((z < 13) ? z : z + 1);
    const float* W = W27 + (size_t)tap * cin * cout;
    const int tid  = threadIdx.x;
    const int scrap = n;

    int myvalid = 0;
    if (tid < 128) {
        int r = row0 + tid;
        int g = -1, s = -1;
        if (r < Mz) {
            if (z == 26) { g = r; s = r; }
            else {
                g = maps[(size_t)z * Mpad + r];
                s = maps[(size_t)(26 + z) * Mpad + r];
            }
        }
        gidx[tid] = g;
        sidx[tid] = s;
        myvalid = (s >= 0 && s != scrap);
    }
    if (__syncthreads_count(myvalid) == 0) return;

    const int lane = tid & 31;
    const int warp = tid >> 5;
    const int wm = (warp & 3) * 32;
    const int wn = (warp >> 2) * (TN / 2);

    const int am0 = tid >> 2, am1 = am0 + 64;
    const int aq  = (tid & 3) * 4;
    const int bn  = tid & (TN - 1);
    const int bk0 = tid / TN;

    float c[2][NI][4];
    #pragma unroll
    for (int mi = 0; mi < 2; mi++)
        #pragma unroll
        for (int ni = 0; ni < NI; ni++)
            #pragma unroll
            for (int j = 0; j < 4; j++) c[mi][ni][j] = 0.f;

    const int g0 = gidx[am0], g1 = gidx[am1];
    float4 av0, av1; float bv[BL];

    av0 = (g0 >= 0) ? *(const float4*)(X + (size_t)g0 * cin + aq) : make_float4(0,0,0,0);
    av1 = (g1 >= 0) ? *(const float4*)(X + (size_t)g1 * cin + aq) : make_float4(0,0,0,0);
    #pragma unroll
    for (int l = 0; l < BL; l++)
        bv[l] = W[(size_t)(bk0 + l * KS) * cout + bn];
    As[0][am0][aq+0] = f2tf32(av0.x); As[0][am0][aq+1] = f2tf32(av0.y);
    As[0][am0][aq+2] = f2tf32(av0.z); As[0][am0][aq+3] = f2tf32(av0.w);
    As[0][am1][aq+0] = f2tf32(av1.x); As[0][am1][aq+1] = f2tf32(av1.y);
    As[0][am1][aq+2] = f2tf32(av1.z); As[0][am1][aq+3] = f2tf32(av1.w);
    #pragma unroll
    for (int l = 0; l < BL; l++) Bs[0][bn][bk0 + l * KS] = f2tf32(bv[l]);
    __syncthreads();

    int buf = 0;
    for (int k0 = 0;; k0 += 16) {
        const bool more = (k0 + 16 < cin);
        if (more) {
            const int kn = k0 + 16;
            av0 = (g0 >= 0) ? *(const float4*)(X + (size_t)g0 * cin + kn + aq) : make_float4(0,0,0,0);
            av1 = (g1 >= 0) ? *(const float4*)(X + (size_t)g1 * cin + kn + aq) : make_float4(0,0,0,0);
            #pragma unroll
            for (int l = 0; l < BL; l++)
                bv[l] = W[(size_t)(kn + bk0 + l * KS) * cout + bn];
        }
        mma_step<NI>(As[buf], Bs[buf], wm, wn, lane, c);
        if (!more) break;
        const int nb2 = buf ^ 1;
        As[nb2][am0][aq+0] = f2tf32(av0.x); As[nb2][am0][aq+1] = f2tf32(av0.y);
        As[nb2][am0][aq+2] = f2tf32(av0.z); As[nb2][am0][aq+3] = f2tf32(av0.w);
        As[nb2][am1][aq+0] = f2tf32(av1.x); As[nb2][am1][aq+1] = f2tf32(av1.y);
        As[nb2][am1][aq+2] = f2tf32(av1.z); As[nb2][am1][aq+3] = f2tf32(av1.w);
        #pragma unroll
        for (int l = 0; l < BL; l++) Bs[nb2][bn][bk0 + l * KS] = f2tf32(bv[l]);
        __syncthreads();
        buf = nb2;
    }

    const int qr = lane >> 2, qc = lane & 3;
    #pragma unroll
    for (int mi = 0; mi < 2; mi++) {
        #pragma unroll
        for (int half = 0; half < 2; half++) {
            const int lr = wm + mi * 16 + qr + half * 8;
            const int o = sidx[lr];
            if (o < 0 || o == scrap) continue;
            float* cp = C + (size_t)o * cout + wn + qc * 2;
            #pragma unroll
            for (int ni = 0; ni < NI; ni++)
                red_add_v2(cp + ni * 8, c[mi][ni][half*2], c[mi][ni][half*2+1]);
        }
    }
}

// ---------------------------------------------------------------------------
// Batched transpose conv (tf32 MMA, TN = cout): T[z*n + r] = X[r] @ Wt[z]
// ---------------------------------------------------------------------------
template<int TN>
__global__ __launch_bounds__(256, 2) void tconv8_t(
    const float* __restrict__ X, const float* __restrict__ W8,
    float* __restrict__ T, int n, int cin)
{
    constexpr int cout = TN;
    constexpr int NI = TN / 16;
    constexpr int BL = TN / 16;
    constexpr int KS = 256 / TN;

    __shared__ unsigned As[2][128][PAD];
    __shared__ unsigned Bs[2][TN][PAD];

    const int z    = blockIdx.y;
    const int row0 = blockIdx.x * 128;
    if (row0 >= n) return;
    const float* W = W8 + (size_t)z * cin * cout;
    const int tid  = threadIdx.x;

    const int lane = tid & 31;
    const int warp = tid >> 5;
    const int wm = (warp & 3) * 32;
    const int wn = (warp >> 2) * (TN / 2);

    const int am0 = tid >> 2, am1 = am0 + 64;
    const int aq  = (tid & 3) * 4;
    const int bn  = tid & (TN - 1);
    const int bk0 = tid / TN;

    const int r0g = row0 + am0, r1g = row0 + am1;
    const long long p0 = (r0g < n) ? (long long)r0g * cin : -1;
    const long long p1 = (r1g < n) ? (long long)r1g * cin : -1;

    float c[2][NI][4];
    #pragma unroll
    for (int mi = 0; mi < 2; mi++)
        #pragma unroll
        for (int ni = 0; ni < NI; ni++)
            #pragma unroll
            for (int j = 0; j < 4; j++) c[mi][ni][j] = 0.f;

    float4 av0, av1; float bv[BL];
    av0 = (p0 >= 0) ? *(const float4*)(X + p0 + aq) : make_float4(0,0,0,0);
    av1 = (p1 >= 0) ? *(const float4*)(X + p1 + aq) : make_float4(0,0,0,0);
    #pragma unroll
    for (int l = 0; l < BL; l++)
        bv[l] = W[(size_t)(bk0 + l * KS) * cout + bn];
    As[0][am0][aq+0] = f2tf32(av0.x); As[0][am0][aq+1] = f2tf32(av0.y);
    As[0][am0][aq+2] = f2tf32(av0.z); As[0][am0][aq+3] = f2tf32(av0.w);
    As[0][am1][aq+0] = f2tf32(av1.x); As[0][am1][aq+1] = f2tf32(av1.y);
    As[0][am1][aq+2] = f2tf32(av1.z); As[0][am1][aq+3] = f2tf32(av1.w);
    #pragma unroll
    for (int l = 0; l < BL; l++) Bs[0][bn][bk0 + l * KS] = f2tf32(bv[l]);
    __syncthreads();

    int buf = 0;
    for (int k0 = 0;; k0 += 16) {
        const bool more = (k0 + 16 < cin);
        if (more) {
            const int kn = k0 + 16;
            av0 = (p0 >= 0) ? *(const float4*)(X + p0 + kn + aq) : make_float4(0,0,0,0);
            av1 = (p1 >= 0) ? *(const float4*)(X + p1 + kn + aq) : make_float4(0,0,0,0);
            #pragma unroll
            for (int l = 0; l < BL; l++)
                bv[l] = W[(size_t)(kn + bk0 + l * KS) * cout + bn];
        }
        mma_step<NI>(As[buf], Bs[buf], wm, wn, lane, c);
        if (!more) break;
        const int nb2 = buf ^ 1;
        As[nb2][am0][aq+0] = f2tf32(av0.x); As[nb2][am0][aq+1] = f2tf32(av0.y);
        As[nb2][am0][aq+2] = f2tf32(av0.z); As[nb2][am0][aq+3] = f2tf32(av0.w);
        As[nb2][am1][aq+0] = f2tf32(av1.x); As[nb2][am1][aq+1] = f2tf32(av1.y);
        As[nb2][am1][aq+2] = f2tf32(av1.z); As[nb2][am1][aq+3] = f2tf32(av1.w);
        #pragma unroll
        for (int l = 0; l < BL; l++) Bs[nb2][bn][bk0 + l * KS] = f2tf32(bv[l]);
        __syncthreads();
        buf = nb2;
    }

    const int qr = lane >> 2, qc = lane & 3;
    #pragma unroll
    for (int mi = 0; mi < 2; mi++) {
        #pragma unroll
        for (int half = 0; half < 2; half++) {
            const int r = row0 + wm + mi * 16 + qr + half * 8;
            if (r >= n) continue;
            float* tp = T + ((size_t)z * n + r) * cout + wn + qc * 2;
            #pragma unroll
            for (int ni = 0; ni < NI; ni++)
                *(float2*)(tp + ni * 8) = make_float2(c[mi][ni][half*2], c[mi][ni][half*2+1]);
        }
    }
}

// ---------------------------------------------------------------------------
// BatchNorm (training-mode batch stats) + ELU
// ---------------------------------------------------------------------------
__global__ void bn_stats(const float* __restrict__ X, int n, int c,
                         float* __restrict__ stats)
{
    int ch = threadIdx.x;
    int r0 = blockIdx.x * 128;
    int rend = r0 + 128; if (rend > n) rend = n;
    float s = 0.f, sq = 0.f;
    for (int r = r0; r < rend; r++) {
        float v = X[(size_t)r * c + ch];
        s += v; sq += v * v;
    }
    atomicAdd(&stats[ch], s);
    atomicAdd(&stats[c + ch], sq);
}

__global__ void bn_apply(const float* __restrict__ X, float* __restrict__ Y,
                         const float* __restrict__ stats,
                         const float* __restrict__ gb, long long total, int n, int c)
{
    long long i = (long long)blockIdx.x * blockDim.x + threadIdx.x;
    if (i >= total) return;
    int ch = (int)(i % c);
    float inv_n = 1.f / (float)n;
    float mu  = stats[ch] * inv_n;
    float var = stats[c + ch] * inv_n - mu * mu;
    float v = gb[ch] * (X[i] - mu) * rsqrtf(var + 1e-5f) + gb[c + ch];
    Y[i] = (v > 0.f) ? v : expm1f(v);
}

// ---------------------------------------------------------------------------
// Sparse-add scatter helpers
// ---------------------------------------------------------------------------
__global__ void scatter_copy(const float* __restrict__ src, float* __restrict__ dst,
                             const int* __restrict__ idx, long long total, int c)
{
    long long i = (long long)blockIdx.x * blockDim.x + threadIdx.x;
    if (i >= total) return;
    int r = (int)(i / c), ch = (int)(i % c);
    dst[(size_t)idx[r] * c + ch] = src[i];
}

__global__ void scatter_add(const float* __restrict__ src, float* __restrict__ dst,
                            const int* __restrict__ idx, long long total, int c)
{
    long long i = (long long)blockIdx.x * blockDim.x + threadIdx.x;
    if (i >= total) return;
    int r = (int)(i / c), ch = (int)(i % c);
    dst[(size_t)idx[r] * c + ch] += src[i];
}

// ---------------------------------------------------------------------------
// Host-side orchestration
// ---------------------------------------------------------------------------
static void sconv3_launch(const float* X, const float* W, const int* m,
                          int n, int Mpad, int cin, int cout, float* acc)
{
    const int ntiles = (n + 127) / 128;
    if (ntiles >= 148) {
        // output-stationary: no atomics, no memset
        dim3 grid(ntiles);
        if (cout == 128)
            conv_gather_t<128><<<grid, 256>>>(X, W, acc, m, Mpad, n, cin);
        else
            conv_gather_t<64><<<grid, 256>>>(X, W, acc, m, Mpad, n, cin);
    } else {
        cudaMemsetAsync(acc, 0, (size_t)(n + 1) * cout * sizeof(float), 0);
        dim3 grid(ntiles, 27);
        if (cout == 128)
            conv_taps_t<128><<<grid, 256>>>(X, W, acc, m, Mpad, n, cin);
        else
            conv_taps_t<64><<<grid, 256>>>(X, W, acc, m, Mpad, n, cin);
    }
}

static void tconv_launch(const float* X, const float* W8, float* T,
                         int n, int cin, int cout)
{
    dim3 grid((n + 127) / 128, 8);
    if (cout == 128)
        tconv8_t<128><<<grid, 256>>>(X, W8, T, n, cin);
    else
        tconv8_t<64><<<grid, 256>>>(X, W8, T, n, cin);
}

static void bn_elu_launch(const float* X, float* Y, const float* gb,
                          int n, int c, float* stats)
{
    cudaMemsetAsync(stats, 0, 2 * c * sizeof(float), 0);
    bn_stats<<<(n + 127) / 128, c>>>(X, n, c, stats);
    long long total = (long long)n * c;
    bn_apply<<<(unsigned)((total + 255) / 256), 256>>>(X, Y, stats, gb, total, n, c);
}

extern "C" void kernel_launch(void* const* d_in, const int* in_sizes, int n_in,
                              void* d_out, int out_size)
{
    const float* feats0 = (const float*)d_in[0];
    const float* feats1 = (const float*)d_in[1];
    const float* feats2 = (const float*)d_in[2];
    const float* w_out0 = (const float*)d_in[3];
    const float* w_out1 = (const float*)d_in[4];
    const float* w_out2 = (const float*)d_in[5];
    const float* wt2    = (const float*)d_in[6];
    const float* wu2    = (const float*)d_in[7];
    const float* wt1    = (const float*)d_in[8];
    const float* wu1    = (const float*)d_in[9];
    const float* bn_out0 = (const float*)d_in[10];
    const float* bn_out1 = (const float*)d_in[11];
    const float* bn_out2 = (const float*)d_in[12];
    const float* bn_up2a = (const float*)d_in[13];
    const float* bn_up2b = (const float*)d_in[14];
    const float* bn_up1a = (const float*)d_in[15];
    const float* bn_up1b = (const float*)d_in[16];
    const int* m_c2 = (const int*)d_in[19];
    const int* m_g2 = (const int*)d_in[20];
    const int* m_u1 = (const int*)d_in[21];
    const int* m_g1 = (const int*)d_in[22];
    const int* m_u0 = (const int*)d_in[23];
    const int* lat1_idx = (const int*)d_in[24];
    const int* up1_idx  = (const int*)d_in[25];
    const int* lat0_idx = (const int*)d_in[26];
    const int* up0_idx  = (const int*)d_in[27];

    const int N0 = in_sizes[0] / 64;
    const int N1 = in_sizes[1] / 128;
    const int N2 = in_sizes[2] / 256;
    const int U1 = in_sizes[17] / 128;
    const int U0 = in_sizes[18] / 64;
    const int Mc2 = in_sizes[19] / 52;
    const int Mg2 = in_sizes[20] / 52;
    const int Mu1 = in_sizes[21] / 52;
    const int Mg1 = in_sizes[22] / 52;
    const int Mu0 = in_sizes[23] / 52;
    const int G2 = 8 * N2;
    const int G1 = 8 * U1;

    float *acc2, *tg2, *accg2, *x1, *acc1, *t1, *accg1, *x0, *acc0, *stats;
    cudaGetSymbolAddress((void**)&acc2,  g_acc2);
    cudaGetSymbolAddress((void**)&tg2,   g_tg2);
    cudaGetSymbolAddress((void**)&accg2, g_accg2);
    cudaGetSymbolAddress((void**)&x1,    g_x1);
    cudaGetSymbolAddress((void**)&acc1,  g_acc1);
    cudaGetSymbolAddress((void**)&t1,    g_t1);
    cudaGetSymbolAddress((void**)&accg1, g_accg1);
    cudaGetSymbolAddress((void**)&x0,    g_x0);
    cudaGetSymbolAddress((void**)&acc0,  g_acc0);
    cudaGetSymbolAddress((void**)&stats, g_stats);

    float* out0 = (float*)d_out;
    float* out1 = out0 + (size_t)U0 * 128;
    float* out2 = out1 + (size_t)U1 * 128;

    // ===== level 2 =====
    sconv3_launch(feats2, w_out2, m_c2, N2, Mc2, 256, 128, acc2);
    bn_elu_launch(acc2, out2, bn_out2, N2, 128, stats);

    // ===== up block 2 =====
    tconv_launch(feats2, wt2, tg2, N2, 256, 128);
    bn_elu_launch(tg2, tg2, bn_up2a, G2, 128, stats);
    sconv3_launch(tg2, wu2, m_g2, G2, Mg2, 128, 128, accg2);
    bn_elu_launch(accg2, accg2, bn_up2b, G2, 128, stats);

    // ===== x1 = union add =====
    cudaMemsetAsync(x1, 0, (size_t)U1 * 128 * sizeof(float), 0);
    {
        long long t = (long long)N1 * 128;
        scatter_copy<<<(unsigned)((t + 255) / 256), 256>>>(feats1, x1, lat1_idx, t, 128);
        t = (long long)G2 * 128;
        scatter_add<<<(unsigned)((t + 255) / 256), 256>>>(accg2, x1, up1_idx, t, 128);
    }

    // ===== out1 =====
    sconv3_launch(x1, w_out1, m_u1, U1, Mu1, 128, 128, acc1);
    bn_elu_launch(acc1, out1, bn_out1, U1, 128, stats);

    // ===== up block 1 =====
    tconv_launch(x1, wt1, t1, U1, 128, 64);
    bn_elu_launch(t1, t1, bn_up1a, G1, 64, stats);
    sconv3_launch(t1, wu1, m_g1, G1, Mg1, 64, 64, accg1);
    bn_elu_launch(accg1, accg1, bn_up1b, G1, 64, stats);

    // ===== x0 = union add =====
    cudaMemsetAsync(x0, 0, (size_t)U0 * 64 * sizeof(float), 0);
    {
        long long t = (long long)N0 * 64;
        scatter_copy<<<(unsigned)((t + 255) / 256), 256>>>(feats0, x0, lat0_idx, t, 64);
        t = (long long)G1 * 64;
        scatter_add<<<(unsigned)((t + 255) / 256), 256>>>(accg1, x0, up0_idx, t, 64);
    }

    // ===== out0 =====
    sconv3_launch(x0, w_out0, m_u0, U0, Mu0, 64, 128, acc0);
    bn_elu_launch(acc0, out0, bn_out0, U0, 128, stats);
}

// round 7
// speedup vs baseline: 1.3566x; 1.3566x over previous
#include <cuda_runtime.h>
#include <math.h>

// ---------------------------------------------------------------------------
// Static scratch (allocation-free per harness rules)
// ---------------------------------------------------------------------------
#define N2MAX 1536
#define G2MAX (8*N2MAX)
#define U1MAX 15872
#define G1MAX (8*U1MAX)
#define U0MAX 160256

__device__ float g_acc2[(N2MAX+1)*128];
__device__ float g_tg2[(size_t)G2MAX*128];
__device__ float g_accg2[((size_t)G2MAX+1)*128];
__device__ float g_x1[(size_t)U1MAX*128];
__device__ float g_acc1[((size_t)U1MAX+1)*128];
__device__ float g_t1[(size_t)G1MAX*64];
__device__ float g_accg1[((size_t)G1MAX+1)*64];
__device__ float g_x0[(size_t)U0MAX*64];
__device__ float g_acc0[((size_t)U0MAX+1)*128];
__device__ float g_stats[8*256];   // per-BN-instance slots (no cross-stream races)

#define PAD 20

__device__ __forceinline__ unsigned f2tf32(float f) {
    unsigned r;
    asm("cvt.rna.tf32.f32 %0, %1;" : "=r"(r) : "f"(f));
    return r;
}

__device__ __forceinline__ void mma_tf32(float& c0, float& c1, float& c2, float& c3,
                                         unsigned a0, unsigned a1, unsigned a2, unsigned a3,
                                         unsigned b0, unsigned b1)
{
    asm volatile("mma.sync.aligned.m16n8k8.row.col.f32.tf32.tf32.f32 "
                 "{%0,%1,%2,%3},{%4,%5,%6,%7},{%8,%9},{%0,%1,%2,%3};"
                 : "+f"(c0), "+f"(c1), "+f"(c2), "+f"(c3)
                 : "r"(a0), "r"(a1), "r"(a2), "r"(a3), "r"(b0), "r"(b1));
}

__device__ __forceinline__ void red_add_v2(float* p, float a, float b) {
    asm volatile("red.global.add.v2.f32 [%0], {%1,%2};"
                 :: "l"(p), "f"(a), "f"(b) : "memory");
}

// ---------------------------------------------------------------------------
// Warp MMA step over one 128 x TN smem tile slice (k = 16).
// ---------------------------------------------------------------------------
template<int NI>
__device__ __forceinline__ void mma_step(const unsigned (*As)[PAD],
                                         const unsigned (*Bs)[PAD],
                                         int wm, int wn, int lane,
                                         float (&c)[2][NI][4])
{
    const int qr = lane >> 2;
    const int qc = lane & 3;
    #pragma unroll
    for (int kt = 0; kt < 2; kt++) {
        const int kb = kt * 8;
        unsigned a[2][4];
        #pragma unroll
        for (int mi = 0; mi < 2; mi++) {
            const int rb = wm + mi * 16 + qr;
            a[mi][0] = As[rb    ][kb + qc];
            a[mi][1] = As[rb + 8][kb + qc];
            a[mi][2] = As[rb    ][kb + qc + 4];
            a[mi][3] = As[rb + 8][kb + qc + 4];
        }
        unsigned b[NI][2];
        #pragma unroll
        for (int ni = 0; ni < NI; ni++) {
            const int nb = wn + ni * 8 + qr;
            b[ni][0] = Bs[nb][kb + qc];
            b[ni][1] = Bs[nb][kb + qc + 4];
        }
        #pragma unroll
        for (int mi = 0; mi < 2; mi++)
            #pragma unroll
            for (int ni = 0; ni < NI; ni++)
                mma_tf32(c[mi][ni][0], c[mi][ni][1], c[mi][ni][2], c[mi][ni][3],
                         a[mi][0], a[mi][1], a[mi][2], a[mi][3], b[ni][0], b[ni][1]);
    }
}

// ---------------------------------------------------------------------------
// Scatter-style tap conv (tf32 MMA + RED).  grid = (ceil(n/128), 27)
// ---------------------------------------------------------------------------
template<int TN>
__global__ __launch_bounds__(256, 2) void conv_taps_t(
    const float* __restrict__ X, const float* __restrict__ W27,
    float* __restrict__ C, const int* __restrict__ maps,
    int Mpad, int n, int cin)
{
    constexpr int cout = TN;
    constexpr int NI = TN / 16;
    constexpr int BL = TN / 16;
    constexpr int KS = 256 / TN;

    __shared__ unsigned As[2][128][PAD];
    __shared__ unsigned Bs[2][TN][PAD];
    __shared__ int gidx[128], sidx[128];

    const int z    = blockIdx.y;
    const int Mz   = (z == 26) ? n : Mpad;
    const int row0 = blockIdx.x * 128;
    if (row0 >= Mz) return;

    const int tap  = (z == 26) ? 13 : ((z < 13) ? z : z + 1);
    const float* W = W27 + (size_t)tap * cin * cout;
    const int tid  = threadIdx.x;
    const int scrap = n;

    int myvalid = 0;
    if (tid < 128) {
        int r = row0 + tid;
        int g = -1, s = -1;
        if (r < Mz) {
            if (z == 26) { g = r; s = r; }
            else {
                g = maps[(size_t)z * Mpad + r];
                s = maps[(size_t)(26 + z) * Mpad + r];
            }
        }
        gidx[tid] = g;
        sidx[tid] = s;
        myvalid = (s >= 0 && s != scrap);
    }
    if (__syncthreads_count(myvalid) == 0) return;

    const int lane = tid & 31;
    const int warp = tid >> 5;
    const int wm = (warp & 3) * 32;
    const int wn = (warp >> 2) * (TN / 2);

    const int am0 = tid >> 2, am1 = am0 + 64;
    const int aq  = (tid & 3) * 4;
    const int bn  = tid & (TN - 1);
    const int bk0 = tid / TN;

    float c[2][NI][4];
    #pragma unroll
    for (int mi = 0; mi < 2; mi++)
        #pragma unroll
        for (int ni = 0; ni < NI; ni++)
            #pragma unroll
            for (int j = 0; j < 4; j++) c[mi][ni][j] = 0.f;

    const int g0 = gidx[am0], g1 = gidx[am1];
    float4 av0, av1; float bv[BL];

    av0 = (g0 >= 0) ? *(const float4*)(X + (size_t)g0 * cin + aq) : make_float4(0,0,0,0);
    av1 = (g1 >= 0) ? *(const float4*)(X + (size_t)g1 * cin + aq) : make_float4(0,0,0,0);
    #pragma unroll
    for (int l = 0; l < BL; l++)
        bv[l] = W[(size_t)(bk0 + l * KS) * cout + bn];
    As[0][am0][aq+0] = f2tf32(av0.x); As[0][am0][aq+1] = f2tf32(av0.y);
    As[0][am0][aq+2] = f2tf32(av0.z); As[0][am0][aq+3] = f2tf32(av0.w);
    As[0][am1][aq+0] = f2tf32(av1.x); As[0][am1][aq+1] = f2tf32(av1.y);
    As[0][am1][aq+2] = f2tf32(av1.z); As[0][am1][aq+3] = f2tf32(av1.w);
    #pragma unroll
    for (int l = 0; l < BL; l++) Bs[0][bn][bk0 + l * KS] = f2tf32(bv[l]);
    __syncthreads();

    int buf = 0;
    for (int k0 = 0;; k0 += 16) {
        const bool more = (k0 + 16 < cin);
        if (more) {
            const int kn = k0 + 16;
            av0 = (g0 >= 0) ? *(const float4*)(X + (size_t)g0 * cin + kn + aq) : make_float4(0,0,0,0);
            av1 = (g1 >= 0) ? *(const float4*)(X + (size_t)g1 * cin + kn + aq) : make_float4(0,0,0,0);
            #pragma unroll
            for (int l = 0; l < BL; l++)
                bv[l] = W[(size_t)(kn + bk0 + l * KS) * cout + bn];
        }
        mma_step<NI>(As[buf], Bs[buf], wm, wn, lane, c);
        if (!more) break;
        const int nb2 = buf ^ 1;
        As[nb2][am0][aq+0] = f2tf32(av0.x); As[nb2][am0][aq+1] = f2tf32(av0.y);
        As[nb2][am0][aq+2] = f2tf32(av0.z); As[nb2][am0][aq+3] = f2tf32(av0.w);
        As[nb2][am1][aq+0] = f2tf32(av1.x); As[nb2][am1][aq+1] = f2tf32(av1.y);
        As[nb2][am1][aq+2] = f2tf32(av1.z); As[nb2][am1][aq+3] = f2tf32(av1.w);
        #pragma unroll
        for (int l = 0; l < BL; l++) Bs[nb2][bn][bk0 + l * KS] = f2tf32(bv[l]);
        __syncthreads();
        buf = nb2;
    }

    const int qr = lane >> 2, qc = lane & 3;
    #pragma unroll
    for (int mi = 0; mi < 2; mi++) {
        #pragma unroll
        for (int half = 0; half < 2; half++) {
            const int lr = wm + mi * 16 + qr + half * 8;
            const int o = sidx[lr];
            if (o < 0 || o == scrap) continue;
            float* cp = C + (size_t)o * cout + wn + qc * 2;
            #pragma unroll
            for (int ni = 0; ni < NI; ni++)
                red_add_v2(cp + ni * 8, c[mi][ni][half*2], c[mi][ni][half*2+1]);
        }
    }
}

// ---------------------------------------------------------------------------
// Batched transpose conv (tf32 MMA): T[z*n + r] = X[r] @ Wt[z]
// ---------------------------------------------------------------------------
template<int TN>
__global__ __launch_bounds__(256, 2) void tconv8_t(
    const float* __restrict__ X, const float* __restrict__ W8,
    float* __restrict__ T, int n, int cin)
{
    constexpr int cout = TN;
    constexpr int NI = TN / 16;
    constexpr int BL = TN / 16;
    constexpr int KS = 256 / TN;

    __shared__ unsigned As[2][128][PAD];
    __shared__ unsigned Bs[2][TN][PAD];

    const int z    = blockIdx.y;
    const int row0 = blockIdx.x * 128;
    if (row0 >= n) return;
    const float* W = W8 + (size_t)z * cin * cout;
    const int tid  = threadIdx.x;

    const int lane = tid & 31;
    const int warp = tid >> 5;
    const int wm = (warp & 3) * 32;
    const int wn = (warp >> 2) * (TN / 2);

    const int am0 = tid >> 2, am1 = am0 + 64;
    const int aq  = (tid & 3) * 4;
    const int bn  = tid & (TN - 1);
    const int bk0 = tid / TN;

    const int r0g = row0 + am0, r1g = row0 + am1;
    const long long p0 = (r0g < n) ? (long long)r0g * cin : -1;
    const long long p1 = (r1g < n) ? (long long)r1g * cin : -1;

    float c[2][NI][4];
    #pragma unroll
    for (int mi = 0; mi < 2; mi++)
        #pragma unroll
        for (int ni = 0; ni < NI; ni++)
            #pragma unroll
            for (int j = 0; j < 4; j++) c[mi][ni][j] = 0.f;

    float4 av0, av1; float bv[BL];
    av0 = (p0 >= 0) ? *(const float4*)(X + p0 + aq) : make_float4(0,0,0,0);
    av1 = (p1 >= 0) ? *(const float4*)(X + p1 + aq) : make_float4(0,0,0,0);
    #pragma unroll
    for (int l = 0; l < BL; l++)
        bv[l] = W[(size_t)(bk0 + l * KS) * cout + bn];
    As[0][am0][aq+0] = f2tf32(av0.x); As[0][am0][aq+1] = f2tf32(av0.y);
    As[0][am0][aq+2] = f2tf32(av0.z); As[0][am0][aq+3] = f2tf32(av0.w);
    As[0][am1][aq+0] = f2tf32(av1.x); As[0][am1][aq+1] = f2tf32(av1.y);
    As[0][am1][aq+2] = f2tf32(av1.z); As[0][am1][aq+3] = f2tf32(av1.w);
    #pragma unroll
    for (int l = 0; l < BL; l++) Bs[0][bn][bk0 + l * KS] = f2tf32(bv[l]);
    __syncthreads();

    int buf = 0;
    for (int k0 = 0;; k0 += 16) {
        const bool more = (k0 + 16 < cin);
        if (more) {
            const int kn = k0 + 16;
            av0 = (p0 >= 0) ? *(const float4*)(X + p0 + kn + aq) : make_float4(0,0,0,0);
            av1 = (p1 >= 0) ? *(const float4*)(X + p1 + kn + aq) : make_float4(0,0,0,0);
            #pragma unroll
            for (int l = 0; l < BL; l++)
                bv[l] = W[(size_t)(kn + bk0 + l * KS) * cout + bn];
        }
        mma_step<NI>(As[buf], Bs[buf], wm, wn, lane, c);
        if (!more) break;
        const int nb2 = buf ^ 1;
        As[nb2][am0][aq+0] = f2tf32(av0.x); As[nb2][am0][aq+1] = f2tf32(av0.y);
        As[nb2][am0][aq+2] = f2tf32(av0.z); As[nb2][am0][aq+3] = f2tf32(av0.w);
        As[nb2][am1][aq+0] = f2tf32(av1.x); As[nb2][am1][aq+1] = f2tf32(av1.y);
        As[nb2][am1][aq+2] = f2tf32(av1.z); As[nb2][am1][aq+3] = f2tf32(av1.w);
        #pragma unroll
        for (int l = 0; l < BL; l++) Bs[nb2][bn][bk0 + l * KS] = f2tf32(bv[l]);
        __syncthreads();
        buf = nb2;
    }

    const int qr = lane >> 2, qc = lane & 3;
    #pragma unroll
    for (int mi = 0; mi < 2; mi++) {
        #pragma unroll
        for (int half = 0; half < 2; half++) {
            const int r = row0 + wm + mi * 16 + qr + half * 8;
            if (r >= n) continue;
            float* tp = T + ((size_t)z * n + r) * cout + wn + qc * 2;
            #pragma unroll
            for (int ni = 0; ni < NI; ni++)
                *(float2*)(tp + ni * 8) = make_float2(c[mi][ni][half*2], c[mi][ni][half*2+1]);
        }
    }
}

// ---------------------------------------------------------------------------
// BatchNorm (training-mode batch stats) + ELU
// ---------------------------------------------------------------------------
__global__ void bn_stats(const float* __restrict__ X, int n, int c,
                         float* __restrict__ stats)
{
    int ch = threadIdx.x;
    int r0 = blockIdx.x * 128;
    int rend = r0 + 128; if (rend > n) rend = n;
    float s = 0.f, sq = 0.f;
    for (int r = r0; r < rend; r++) {
        float v = X[(size_t)r * c + ch];
        s += v; sq += v * v;
    }
    atomicAdd(&stats[ch], s);
    atomicAdd(&stats[c + ch], sq);
}

__global__ void bn_apply(const float* __restrict__ X, float* __restrict__ Y,
                         const float* __restrict__ stats,
                         const float* __restrict__ gb, long long total, int n, int c)
{
    long long i = (long long)blockIdx.x * blockDim.x + threadIdx.x;
    if (i >= total) return;
    int ch = (int)(i % c);
    float inv_n = 1.f / (float)n;
    float mu  = stats[ch] * inv_n;
    float var = stats[c + ch] * inv_n - mu * mu;
    float v = gb[ch] * (X[i] - mu) * rsqrtf(var + 1e-5f) + gb[c + ch];
    Y[i] = (v > 0.f) ? v : expm1f(v);
}

// Fused: DST[idx[r]] += elu(bn(X[r]))  (idx rows unique -> plain +=)
__global__ void bn_apply_add(const float* __restrict__ X, float* __restrict__ DST,
                             const int* __restrict__ idx,
                             const float* __restrict__ stats,
                             const float* __restrict__ gb, long long total, int n, int c)
{
    long long i = (long long)blockIdx.x * blockDim.x + threadIdx.x;
    if (i >= total) return;
    int r = (int)(i / c), ch = (int)(i % c);
    float inv_n = 1.f / (float)n;
    float mu  = stats[ch] * inv_n;
    float var = stats[c + ch] * inv_n - mu * mu;
    float v = gb[ch] * (X[i] - mu) * rsqrtf(var + 1e-5f) + gb[c + ch];
    v = (v > 0.f) ? v : expm1f(v);
    DST[(size_t)idx[r] * c + ch] += v;
}

__global__ void scatter_copy(const float* __restrict__ src, float* __restrict__ dst,
                             const int* __restrict__ idx, long long total, int c)
{
    long long i = (long long)blockIdx.x * blockDim.x + threadIdx.x;
    if (i >= total) return;
    int r = (int)(i / c), ch = (int)(i % c);
    dst[(size_t)idx[r] * c + ch] = src[i];
}

// ---------------------------------------------------------------------------
// Host-side orchestration (two-stream fork/join under graph capture)
// ---------------------------------------------------------------------------
static void sconv3_launch(const float* X, const float* W, const int* m,
                          int n, int Mpad, int cin, int cout, float* acc,
                          cudaStream_t st)
{
    cudaMemsetAsync(acc, 0, (size_t)(n + 1) * cout * sizeof(float), st);
    dim3 grid((n + 127) / 128, 27);
    if (cout == 128)
        conv_taps_t<128><<<grid, 256, 0, st>>>(X, W, acc, m, Mpad, n, cin);
    else
        conv_taps_t<64><<<grid, 256, 0, st>>>(X, W, acc, m, Mpad, n, cin);
}

static void tconv_launch(const float* X, const float* W8, float* T,
                         int n, int cin, int cout, cudaStream_t st)
{
    dim3 grid((n + 127) / 128, 8);
    if (cout == 128)
        tconv8_t<128><<<grid, 256, 0, st>>>(X, W8, T, n, cin);
    else
        tconv8_t<64><<<grid, 256, 0, st>>>(X, W8, T, n, cin);
}

static void bn_stats_launch(const float* X, int n, int c, float* stats, cudaStream_t st)
{
    cudaMemsetAsync(stats, 0, 2 * c * sizeof(float), st);
    bn_stats<<<(n + 127) / 128, c, 0, st>>>(X, n, c, stats);
}

static void bn_elu_launch(const float* X, float* Y, const float* gb,
                          int n, int c, float* stats, cudaStream_t st)
{
    bn_stats_launch(X, n, c, stats, st);
    long long total = (long long)n * c;
    bn_apply<<<(unsigned)((total + 255) / 256), 256, 0, st>>>(X, Y, stats, gb, total, n, c);
}

extern "C" void kernel_launch(void* const* d_in, const int* in_sizes, int n_in,
                              void* d_out, int out_size)
{
    const float* feats0 = (const float*)d_in[0];
    const float* feats1 = (const float*)d_in[1];
    const float* feats2 = (const float*)d_in[2];
    const float* w_out0 = (const float*)d_in[3];
    const float* w_out1 = (const float*)d_in[4];
    const float* w_out2 = (const float*)d_in[5];
    const float* wt2    = (const float*)d_in[6];
    const float* wu2    = (const float*)d_in[7];
    const float* wt1    = (const float*)d_in[8];
    const float* wu1    = (const float*)d_in[9];
    const float* bn_out0 = (const float*)d_in[10];
    const float* bn_out1 = (const float*)d_in[11];
    const float* bn_out2 = (const float*)d_in[12];
    const float* bn_up2a = (const float*)d_in[13];
    const float* bn_up2b = (const float*)d_in[14];
    const float* bn_up1a = (const float*)d_in[15];
    const float* bn_up1b = (const float*)d_in[16];
    const int* m_c2 = (const int*)d_in[19];
    const int* m_g2 = (const int*)d_in[20];
    const int* m_u1 = (const int*)d_in[21];
    const int* m_g1 = (const int*)d_in[22];
    const int* m_u0 = (const int*)d_in[23];
    const int* lat1_idx = (const int*)d_in[24];
    const int* up1_idx  = (const int*)d_in[25];
    const int* lat0_idx = (const int*)d_in[26];
    const int* up0_idx  = (const int*)d_in[27];

    const int N0 = in_sizes[0] / 64;
    const int N1 = in_sizes[1] / 128;
    const int N2 = in_sizes[2] / 256;
    const int U1 = in_sizes[17] / 128;
    const int U0 = in_sizes[18] / 64;
    const int Mc2 = in_sizes[19] / 52;
    const int Mg2 = in_sizes[20] / 52;
    const int Mu1 = in_sizes[21] / 52;
    const int Mg1 = in_sizes[22] / 52;
    const int Mu0 = in_sizes[23] / 52;
    const int G2 = 8 * N2;
    const int G1 = 8 * U1;

    float *acc2, *tg2, *accg2, *x1, *acc1, *t1, *accg1, *x0, *acc0, *stats;
    cudaGetSymbolAddress((void**)&acc2,  g_acc2);
    cudaGetSymbolAddress((void**)&tg2,   g_tg2);
    cudaGetSymbolAddress((void**)&accg2, g_accg2);
    cudaGetSymbolAddress((void**)&x1,    g_x1);
    cudaGetSymbolAddress((void**)&acc1,  g_acc1);
    cudaGetSymbolAddress((void**)&t1,    g_t1);
    cudaGetSymbolAddress((void**)&accg1, g_accg1);
    cudaGetSymbolAddress((void**)&x0,    g_x0);
    cudaGetSymbolAddress((void**)&acc0,  g_acc0);
    cudaGetSymbolAddress((void**)&stats, g_stats);

    float* out0 = (float*)d_out;
    float* out1 = out0 + (size_t)U0 * 128;
    float* out2 = out1 + (size_t)U1 * 128;

    // streams/events created once; handles don't change the captured work
    static cudaStream_t s1 = nullptr;
    static cudaEvent_t eRoot = nullptr, eX1 = nullptr, eEnd = nullptr;
    if (!s1) {
        cudaStreamCreateWithFlags(&s1, cudaStreamNonBlocking);
        cudaEventCreateWithFlags(&eRoot, cudaEventDisableTiming);
        cudaEventCreateWithFlags(&eX1,   cudaEventDisableTiming);
        cudaEventCreateWithFlags(&eEnd,  cudaEventDisableTiming);
    }
    cudaStream_t s0 = 0;

    // ---- fork ----
    cudaEventRecord(eRoot, s0);
    cudaStreamWaitEvent(s1, eRoot, 0);

    // ===== stream0: out2 head (independent of up path) =====
    sconv3_launch(feats2, w_out2, m_c2, N2, Mc2, 256, 128, acc2, s0);
    bn_elu_launch(acc2, out2, bn_out2, N2, 128, stats + 0*256, s0);

    // ===== s1: union bases + up path =====
    cudaMemsetAsync(x1, 0, (size_t)U1 * 128 * sizeof(float), s1);
    {
        long long t = (long long)N1 * 128;
        scatter_copy<<<(unsigned)((t + 255) / 256), 256, 0, s1>>>(feats1, x1, lat1_idx, t, 128);
    }
    cudaMemsetAsync(x0, 0, (size_t)U0 * 64 * sizeof(float), s1);
    {
        long long t = (long long)N0 * 64;
        scatter_copy<<<(unsigned)((t + 255) / 256), 256, 0, s1>>>(feats0, x0, lat0_idx, t, 64);
    }

    // up block 2: tconv -> bn -> conv3 -> fused bn+add into x1
    tconv_launch(feats2, wt2, tg2, N2, 256, 128, s1);
    bn_elu_launch(tg2, tg2, bn_up2a, G2, 128, stats + 1*256, s1);
    sconv3_launch(tg2, wu2, m_g2, G2, Mg2, 128, 128, accg2, s1);
    bn_stats_launch(accg2, G2, 128, stats + 2*256, s1);
    {
        long long t = (long long)G2 * 128;
        bn_apply_add<<<(unsigned)((t + 255) / 256), 256, 0, s1>>>(
            accg2, x1, up1_idx, stats + 2*256, bn_up2b, t, G2, 128);
    }
    cudaEventRecord(eX1, s1);   // x1 complete

    // up block 1 (continues on s1)
    tconv_launch(x1, wt1, t1, U1, 128, 64, s1);
    bn_elu_launch(t1, t1, bn_up1a, G1, 64, stats + 3*256, s1);
    sconv3_launch(t1, wu1, m_g1, G1, Mg1, 64, 64, accg1, s1);
    bn_stats_launch(accg1, G1, 64, stats + 4*256, s1);
    {
        long long t = (long long)G1 * 64;
        bn_apply_add<<<(unsigned)((t + 255) / 256), 256, 0, s1>>>(
            accg1, x0, up0_idx, stats + 4*256, bn_up1b, t, G1, 64);
    }
    // out0 head (on s1; depends on x0 only)
    sconv3_launch(x0, w_out0, m_u0, U0, Mu0, 64, 128, acc0, s1);
    bn_elu_launch(acc0, out0, bn_out0, U0, 128, stats + 5*256, s1);
    cudaEventRecord(eEnd, s1);

    // ===== stream0: out1 head, overlapping s1's up-block-1 =====
    cudaStreamWaitEvent(s0, eX1, 0);
    sconv3_launch(x1, w_out1, m_u1, U1, Mu1, 128, 128, acc1, s0);
    bn_elu_launch(acc1, out1, bn_out1, U1, 128, stats + 6*256, s0);

    // ---- join ----
    cudaStreamWaitEvent(s0, eEnd, 0);
}

// round 8
// speedup vs baseline: 1.3730x; 1.0121x over previous
#include <cuda_runtime.h>
#include <math.h>

// ---------------------------------------------------------------------------
// Static scratch (allocation-free per harness rules)
// ---------------------------------------------------------------------------
#define N2MAX 1536
#define G2MAX (8*N2MAX)
#define U1MAX 15872
#define G1MAX (8*U1MAX)
#define U0MAX 160256

__device__ float g_acc2[(N2MAX+1)*128];
__device__ float g_tg2[(size_t)G2MAX*128];
__device__ float g_accg2[((size_t)G2MAX+1)*128];
__device__ float g_x1[(size_t)U1MAX*128];
__device__ float g_acc1[((size_t)U1MAX+1)*128];
__device__ float g_t1[(size_t)G1MAX*64];
__device__ float g_accg1[((size_t)G1MAX+1)*64];
__device__ float g_x0[(size_t)U0MAX*64];
__device__ float g_acc0[((size_t)U0MAX+1)*128];
__device__ float g_stats[8*256];

#define ASTR 68          // As row stride (words): frag reads + f4 stores conflict-free

__device__ __forceinline__ unsigned f2tf32(float f) {
    unsigned r;
    asm("cvt.rna.tf32.f32 %0, %1;" : "=r"(r) : "f"(f));
    return r;
}

__device__ __forceinline__ void mma_tf32(float& c0, float& c1, float& c2, float& c3,
                                         unsigned a0, unsigned a1, unsigned a2, unsigned a3,
                                         unsigned b0, unsigned b1)
{
    asm volatile("mma.sync.aligned.m16n8k8.row.col.f32.tf32.tf32.f32 "
                 "{%0,%1,%2,%3},{%4,%5,%6,%7},{%8,%9},{%0,%1,%2,%3};"
                 : "+f"(c0), "+f"(c1), "+f"(c2), "+f"(c3)
                 : "r"(a0), "r"(a1), "r"(a2), "r"(a3), "r"(b0), "r"(b1));
}

__device__ __forceinline__ void red_add_v2(float* p, float a, float b) {
    asm volatile("red.global.add.v2.f32 [%0], {%1,%2};"
                 :: "l"(p), "f"(a), "f"(b) : "memory");
}

// ---------------------------------------------------------------------------
// Core: one 64-wide k-chunk resident in smem, 8 uninterrupted MMA k-slices.
// As[128][ASTR] (m-major), Bs[64][TN+4] (k-major). Warps 4(m) x 2(n).
// ---------------------------------------------------------------------------
template<int TN>
__device__ __forceinline__ void mma_chunk(const unsigned (*As)[ASTR],
                                          const unsigned (*Bs)[TN + 4],
                                          int wm, int wn, int lane,
                                          float (&c)[2][TN/16][4])
{
    constexpr int NI = TN / 16;
    const int qr = lane >> 2;
    const int qc = lane & 3;
    #pragma unroll
    for (int kt = 0; kt < 8; kt++) {
        const int kb = kt * 8;
        unsigned a[2][4];
        #pragma unroll
        for (int mi = 0; mi < 2; mi++) {
            const int rb = wm + mi * 16 + qr;
            a[mi][0] = As[rb    ][kb + qc];
            a[mi][1] = As[rb + 8][kb + qc];
            a[mi][2] = As[rb    ][kb + qc + 4];
            a[mi][3] = As[rb + 8][kb + qc + 4];
        }
        unsigned b[NI][2];
        #pragma unroll
        for (int ni = 0; ni < NI; ni++) {
            const int nb = wn + ni * 8 + qr;
            b[ni][0] = Bs[kb + qc    ][nb];
            b[ni][1] = Bs[kb + qc + 4][nb];
        }
        #pragma unroll
        for (int mi = 0; mi < 2; mi++)
            #pragma unroll
            for (int ni = 0; ni < NI; ni++)
                mma_tf32(c[mi][ni][0], c[mi][ni][1], c[mi][ni][2], c[mi][ni][3],
                         a[mi][0], a[mi][1], a[mi][2], a[mi][3], b[ni][0], b[ni][1]);
    }
}

// Load A chunk (gathered rows, 64 k) + B chunk (64 x TN) into smem.
template<int TN>
__device__ __forceinline__ void load_chunk(
    const float* __restrict__ X, const float* __restrict__ W,
    const int* rowsrc, int cin, int kc,
    unsigned (*As)[ASTR], unsigned (*Bs)[TN + 4], int tid)
{
    const int mrow = tid >> 4;        // 0..15
    const int q4   = (tid & 15) * 4;  // k offset (f4)
    #pragma unroll
    for (int p = 0; p < 8; p++) {
        const int m = p * 16 + mrow;
        const int g = rowsrc[m];
        float4 v = make_float4(0.f, 0.f, 0.f, 0.f);
        if (g >= 0) v = *(const float4*)(X + (size_t)g * cin + kc + q4);
        As[m][q4 + 0] = f2tf32(v.x);
        As[m][q4 + 1] = f2tf32(v.y);
        As[m][q4 + 2] = f2tf32(v.z);
        As[m][q4 + 3] = f2tf32(v.w);
    }
    constexpr int N4 = TN / 4;
    #pragma unroll
    for (int l = 0; l < TN / 16; l++) {
        const int idx = tid + l * 256;     // over 16*TN f4 slots
        const int n4 = idx % N4;
        const int k  = idx / N4;           // 0..63
        const float4 v = *(const float4*)(W + (size_t)(kc + k) * TN + n4 * 4);
        Bs[k][n4 * 4 + 0] = f2tf32(v.x);
        Bs[k][n4 * 4 + 1] = f2tf32(v.y);
        Bs[k][n4 * 4 + 2] = f2tf32(v.z);
        Bs[k][n4 * 4 + 3] = f2tf32(v.w);
    }
}

// ---------------------------------------------------------------------------
// Scatter-style tap conv.  grid = (ceil(n/128), 27)
// ---------------------------------------------------------------------------
template<int TN, int MAXCTA>
__global__ __launch_bounds__(256, MAXCTA) void conv3(
    const float* __restrict__ X, const float* __restrict__ W27,
    float* __restrict__ C, const int* __restrict__ maps,
    int Mpad, int n, int cin)
{
    constexpr int NI = TN / 16;
    __shared__ unsigned As[128][ASTR];
    __shared__ unsigned Bs[64][TN + 4];
    __shared__ int gidx[128], sidx[128];

    const int z    = blockIdx.y;
    const int Mz   = (z == 26) ? n : Mpad;
    const int row0 = blockIdx.x * 128;
    if (row0 >= Mz) return;

    const int tap  = (z == 26) ? 13 : ((z < 13) ? z : z + 1);
    const float* W = W27 + (size_t)tap * cin * TN;
    const int tid  = threadIdx.x;
    const int scrap = n;

    int myvalid = 0;
    if (tid < 128) {
        int r = row0 + tid;
        int g = -1, s = -1;
        if (r < Mz) {
            if (z == 26) { g = r; s = r; }
            else {
                g = maps[(size_t)z * Mpad + r];
                s = maps[(size_t)(26 + z) * Mpad + r];
            }
        }
        gidx[tid] = g;
        sidx[tid] = s;
        myvalid = (s >= 0 && s != scrap);
    }
    if (__syncthreads_count(myvalid) == 0) return;

    const int lane = tid & 31;
    const int warp = tid >> 5;
    const int wm = (warp & 3) * 32;
    const int wn = (warp >> 2) * (TN / 2);

    float c[2][NI][4];
    #pragma unroll
    for (int mi = 0; mi < 2; mi++)
        #pragma unroll
        for (int ni = 0; ni < NI; ni++)
            #pragma unroll
            for (int j = 0; j < 4; j++) c[mi][ni][j] = 0.f;

    for (int kc = 0; kc < cin; kc += 64) {
        if (kc) __syncthreads();
        load_chunk<TN>(X, W, gidx, cin, kc, As, Bs, tid);
        __syncthreads();
        mma_chunk<TN>(As, Bs, wm, wn, lane, c);
    }

    const int qr = lane >> 2, qc = lane & 3;
    #pragma unroll
    for (int mi = 0; mi < 2; mi++) {
        #pragma unroll
        for (int half = 0; half < 2; half++) {
            const int lr = wm + mi * 16 + qr + half * 8;
            const int o = sidx[lr];
            if (o < 0 || o == scrap) continue;
            float* cp = C + (size_t)o * TN + wn + qc * 2;
            #pragma unroll
            for (int ni = 0; ni < NI; ni++)
                red_add_v2(cp + ni * 8, c[mi][ni][half*2], c[mi][ni][half*2+1]);
        }
    }
}

// ---------------------------------------------------------------------------
// Batched transpose conv: T[z*n + r] = X[r] @ Wt[z].  grid = (ceil(n/128), 8)
// ---------------------------------------------------------------------------
template<int TN, int MAXCTA>
__global__ __launch_bounds__(256, MAXCTA) void tconv3(
    const float* __restrict__ X, const float* __restrict__ W8,
    float* __restrict__ T, int n, int cin)
{
    constexpr int NI = TN / 16;
    __shared__ unsigned As[128][ASTR];
    __shared__ unsigned Bs[64][TN + 4];
    __shared__ int gidx[128];

    const int z    = blockIdx.y;
    const int row0 = blockIdx.x * 128;
    if (row0 >= n) return;
    const float* W = W8 + (size_t)z * cin * TN;
    const int tid  = threadIdx.x;

    if (tid < 128) {
        int r = row0 + tid;
        gidx[tid] = (r < n) ? r : -1;
    }
    __syncthreads();

    const int lane = tid & 31;
    const int warp = tid >> 5;
    const int wm = (warp & 3) * 32;
    const int wn = (warp >> 2) * (TN / 2);

    float c[2][NI][4];
    #pragma unroll
    for (int mi = 0; mi < 2; mi++)
        #pragma unroll
        for (int ni = 0; ni < NI; ni++)
            #pragma unroll
            for (int j = 0; j < 4; j++) c[mi][ni][j] = 0.f;

    for (int kc = 0; kc < cin; kc += 64) {
        if (kc) __syncthreads();
        load_chunk<TN>(X, W, gidx, cin, kc, As, Bs, tid);
        __syncthreads();
        mma_chunk<TN>(As, Bs, wm, wn, lane, c);
    }

    const int qr = lane >> 2, qc = lane & 3;
    #pragma unroll
    for (int mi = 0; mi < 2; mi++) {
        #pragma unroll
        for (int half = 0; half < 2; half++) {
            const int r = row0 + wm + mi * 16 + qr + half * 8;
            if (r >= n) continue;
            float* tp = T + ((size_t)z * n + r) * TN + wn + qc * 2;
            #pragma unroll
            for (int ni = 0; ni < NI; ni++)
                *(float2*)(tp + ni * 8) = make_float2(c[mi][ni][half*2], c[mi][ni][half*2+1]);
        }
    }
}

// ---------------------------------------------------------------------------
// BatchNorm (training-mode batch stats) + ELU
// ---------------------------------------------------------------------------
__global__ void bn_stats(const float* __restrict__ X, int n, int c,
                         float* __restrict__ stats)
{
    int ch = threadIdx.x;
    int r0 = blockIdx.x * 128;
    int rend = r0 + 128; if (rend > n) rend = n;
    float s = 0.f, sq = 0.f;
    for (int r = r0; r < rend; r++) {
        float v = X[(size_t)r * c + ch];
        s += v; sq += v * v;
    }
    atomicAdd(&stats[ch], s);
    atomicAdd(&stats[c + ch], sq);
}

__global__ void bn_apply(const float* __restrict__ X, float* __restrict__ Y,
                         const float* __restrict__ stats,
                         const float* __restrict__ gb, long long total, int n, int c)
{
    long long i = (long long)blockIdx.x * blockDim.x + threadIdx.x;
    if (i >= total) return;
    int ch = (int)(i % c);
    float inv_n = 1.f / (float)n;
    float mu  = stats[ch] * inv_n;
    float var = stats[c + ch] * inv_n - mu * mu;
    float v = gb[ch] * (X[i] - mu) * rsqrtf(var + 1e-5f) + gb[c + ch];
    Y[i] = (v > 0.f) ? v : expm1f(v);
}

// Fused: DST[idx[r]] += elu(bn(X[r]))
__global__ void bn_apply_add(const float* __restrict__ X, float* __restrict__ DST,
                             const int* __restrict__ idx,
                             const float* __restrict__ stats,
                             const float* __restrict__ gb, long long total, int n, int c)
{
    long long i = (long long)blockIdx.x * blockDim.x + threadIdx.x;
    if (i >= total) return;
    int r = (int)(i / c), ch = (int)(i % c);
    float inv_n = 1.f / (float)n;
    float mu  = stats[ch] * inv_n;
    float var = stats[c + ch] * inv_n - mu * mu;
    float v = gb[ch] * (X[i] - mu) * rsqrtf(var + 1e-5f) + gb[c + ch];
    v = (v > 0.f) ? v : expm1f(v);
    DST[(size_t)idx[r] * c + ch] += v;
}

__global__ void scatter_copy(const float* __restrict__ src, float* __restrict__ dst,
                             const int* __restrict__ idx, long long total, int c)
{
    long long i = (long long)blockIdx.x * blockDim.x + threadIdx.x;
    if (i >= total) return;
    int r = (int)(i / c), ch = (int)(i % c);
    dst[(size_t)idx[r] * c + ch] = src[i];
}

// ---------------------------------------------------------------------------
// Host-side orchestration (two-stream fork/join under graph capture)
// ---------------------------------------------------------------------------
static void sconv3_launch(const float* X, const float* W, const int* m,
                          int n, int Mpad, int cin, int cout, float* acc,
                          cudaStream_t st)
{
    cudaMemsetAsync(acc, 0, (size_t)(n + 1) * cout * sizeof(float), st);
    dim3 grid((n + 127) / 128, 27);
    if (cout == 128)
        conv3<128, 2><<<grid, 256, 0, st>>>(X, W, acc, m, Mpad, n, cin);
    else
        conv3<64, 3><<<grid, 256, 0, st>>>(X, W, acc, m, Mpad, n, cin);
}

static void tconv_launch(const float* X, const float* W8, float* T,
                         int n, int cin, int cout, cudaStream_t st)
{
    dim3 grid((n + 127) / 128, 8);
    if (cout == 128)
        tconv3<128, 2><<<grid, 256, 0, st>>>(X, W8, T, n, cin);
    else
        tconv3<64, 3><<<grid, 256, 0, st>>>(X, W8, T, n, cin);
}

static void bn_stats_launch(const float* X, int n, int c, float* stats, cudaStream_t st)
{
    cudaMemsetAsync(stats, 0, 2 * c * sizeof(float), st);
    bn_stats<<<(n + 127) / 128, c, 0, st>>>(X, n, c, stats);
}

static void bn_elu_launch(const float* X, float* Y, const float* gb,
                          int n, int c, float* stats, cudaStream_t st)
{
    bn_stats_launch(X, n, c, stats, st);
    long long total = (long long)n * c;
    bn_apply<<<(unsigned)((total + 255) / 256), 256, 0, st>>>(X, Y, stats, gb, total, n, c);
}

extern "C" void kernel_launch(void* const* d_in, const int* in_sizes, int n_in,
                              void* d_out, int out_size)
{
    const float* feats0 = (const float*)d_in[0];
    const float* feats1 = (const float*)d_in[1];
    const float* feats2 = (const float*)d_in[2];
    const float* w_out0 = (const float*)d_in[3];
    const float* w_out1 = (const float*)d_in[4];
    const float* w_out2 = (const float*)d_in[5];
    const float* wt2    = (const float*)d_in[6];
    const float* wu2    = (const float*)d_in[7];
    const float* wt1    = (const float*)d_in[8];
    const float* wu1    = (const float*)d_in[9];
    const float* bn_out0 = (const float*)d_in[10];
    const float* bn_out1 = (const float*)d_in[11];
    const float* bn_out2 = (const float*)d_in[12];
    const float* bn_up2a = (const float*)d_in[13];
    const float* bn_up2b = (const float*)d_in[14];
    const float* bn_up1a = (const float*)d_in[15];
    const float* bn_up1b = (const float*)d_in[16];
    const int* m_c2 = (const int*)d_in[19];
    const int* m_g2 = (const int*)d_in[20];
    const int* m_u1 = (const int*)d_in[21];
    const int* m_g1 = (const int*)d_in[22];
    const int* m_u0 = (const int*)d_in[23];
    const int* lat1_idx = (const int*)d_in[24];
    const int* up1_idx  = (const int*)d_in[25];
    const int* lat0_idx = (const int*)d_in[26];
    const int* up0_idx  = (const int*)d_in[27];

    const int N0 = in_sizes[0] / 64;
    const int N1 = in_sizes[1] / 128;
    const int N2 = in_sizes[2] / 256;
    const int U1 = in_sizes[17] / 128;
    const int U0 = in_sizes[18] / 64;
    const int Mc2 = in_sizes[19] / 52;
    const int Mg2 = in_sizes[20] / 52;
    const int Mu1 = in_sizes[21] / 52;
    const int Mg1 = in_sizes[22] / 52;
    const int Mu0 = in_sizes[23] / 52;
    const int G2 = 8 * N2;
    const int G1 = 8 * U1;

    float *acc2, *tg2, *accg2, *x1, *acc1, *t1, *accg1, *x0, *acc0, *stats;
    cudaGetSymbolAddress((void**)&acc2,  g_acc2);
    cudaGetSymbolAddress((void**)&tg2,   g_tg2);
    cudaGetSymbolAddress((void**)&accg2, g_accg2);
    cudaGetSymbolAddress((void**)&x1,    g_x1);
    cudaGetSymbolAddress((void**)&acc1,  g_acc1);
    cudaGetSymbolAddress((void**)&t1,    g_t1);
    cudaGetSymbolAddress((void**)&accg1, g_accg1);
    cudaGetSymbolAddress((void**)&x0,    g_x0);
    cudaGetSymbolAddress((void**)&acc0,  g_acc0);
    cudaGetSymbolAddress((void**)&stats, g_stats);

    float* out0 = (float*)d_out;
    float* out1 = out0 + (size_t)U0 * 128;
    float* out2 = out1 + (size_t)U1 * 128;

    static cudaStream_t s1 = nullptr;
    static cudaEvent_t eRoot = nullptr, eX1 = nullptr, eEnd = nullptr;
    if (!s1) {
        cudaStreamCreateWithFlags(&s1, cudaStreamNonBlocking);
        cudaEventCreateWithFlags(&eRoot, cudaEventDisableTiming);
        cudaEventCreateWithFlags(&eX1,   cudaEventDisableTiming);
        cudaEventCreateWithFlags(&eEnd,  cudaEventDisableTiming);
    }
    cudaStream_t s0 = 0;

    // ---- fork ----
    cudaEventRecord(eRoot, s0);
    cudaStreamWaitEvent(s1, eRoot, 0);

    // ===== stream0: out2 head =====
    sconv3_launch(feats2, w_out2, m_c2, N2, Mc2, 256, 128, acc2, s0);
    bn_elu_launch(acc2, out2, bn_out2, N2, 128, stats + 0*256, s0);

    // ===== s1: union bases + up path =====
    cudaMemsetAsync(x1, 0, (size_t)U1 * 128 * sizeof(float), s1);
    {
        long long t = (long long)N1 * 128;
        scatter_copy<<<(unsigned)((t + 255) / 256), 256, 0, s1>>>(feats1, x1, lat1_idx, t, 128);
    }
    cudaMemsetAsync(x0, 0, (size_t)U0 * 64 * sizeof(float), s1);
    {
        long long t = (long long)N0 * 64;
        scatter_copy<<<(unsigned)((t + 255) / 256), 256, 0, s1>>>(feats0, x0, lat0_idx, t, 64);
    }

    // up block 2
    tconv_launch(feats2, wt2, tg2, N2, 256, 128, s1);
    bn_elu_launch(tg2, tg2, bn_up2a, G2, 128, stats + 1*256, s1);
    sconv3_launch(tg2, wu2, m_g2, G2, Mg2, 128, 128, accg2, s1);
    bn_stats_launch(accg2, G2, 128, stats + 2*256, s1);
    {
        long long t = (long long)G2 * 128;
        bn_apply_add<<<(unsigned)((t + 255) / 256), 256, 0, s1>>>(
            accg2, x1, up1_idx, stats + 2*256, bn_up2b, t, G2, 128);
    }
    cudaEventRecord(eX1, s1);

    // up block 1
    tconv_launch(x1, wt1, t1, U1, 128, 64, s1);
    bn_elu_launch(t1, t1, bn_up1a, G1, 64, stats + 3*256, s1);
    sconv3_launch(t1, wu1, m_g1, G1, Mg1, 64, 64, accg1, s1);
    bn_stats_launch(accg1, G1, 64, stats + 4*256, s1);
    {
        long long t = (long long)G1 * 64;
        bn_apply_add<<<(unsigned)((t + 255) / 256), 256, 0, s1>>>(
            accg1, x0, up0_idx, stats + 4*256, bn_up1b, t, G1, 64);
    }
    // out0 head
    sconv3_launch(x0, w_out0, m_u0, U0, Mu0, 64, 128, acc0, s1);
    bn_elu_launch(acc0, out0, bn_out0, U0, 128, stats + 5*256, s1);
    cudaEventRecord(eEnd, s1);

    // ===== stream0: out1 head, overlapping up-block-1 =====
    cudaStreamWaitEvent(s0, eX1, 0);
    sconv3_launch(x1, w_out1, m_u1, U1, Mu1, 128, 128, acc1, s0);
    bn_elu_launch(acc1, out1, bn_out1, U1, 128, stats + 6*256, s0);

    // ---- join ----
    cudaStreamWaitEvent(s0, eEnd, 0);
}

// round 9
// speedup vs baseline: 1.4291x; 1.0409x over previous
#include <cuda_runtime.h>
#include <math.h>

// ---------------------------------------------------------------------------
// Static scratch (allocation-free per harness rules)
// ---------------------------------------------------------------------------
#define N2MAX 1536
#define G2MAX (8*N2MAX)
#define U1MAX 15872
#define G1MAX (8*U1MAX)
#define U0MAX 160256

__device__ float g_acc2[(N2MAX+1)*128];
__device__ float g_tg2[(size_t)G2MAX*128];
__device__ float g_accg2[((size_t)G2MAX+1)*128];
__device__ float g_x1[(size_t)U1MAX*128];
__device__ float g_acc1[((size_t)U1MAX+1)*128];
__device__ float g_t1[(size_t)G1MAX*64];
__device__ float g_accg1[((size_t)G1MAX+1)*64];
__device__ float g_x0[(size_t)U0MAX*64];
__device__ float g_acc0[((size_t)U0MAX+1)*128];
__device__ float g_stats[8*256];

// rounded (tf32-in-f32) weights, concatenated + rounded feats2
__device__ float g_wr[2428928];
__device__ float g_f2r[(size_t)N2MAX*256];

#define O_WOUT0 0
#define O_WOUT1 221184
#define O_WOUT2 663552
#define O_WT2   1548288
#define O_WU2   1810432
#define O_WT1   2252800
#define O_WU1   2318336

#define ASTR 68

__device__ __forceinline__ unsigned f2tf32(float f) {
    unsigned r;
    asm("cvt.rna.tf32.f32 %0, %1;" : "=r"(r) : "f"(f));
    return r;
}
__device__ __forceinline__ float rnd_tf32(float f) { return __uint_as_float(f2tf32(f)); }

__device__ __forceinline__ void mma_tf32(float& c0, float& c1, float& c2, float& c3,
                                         unsigned a0, unsigned a1, unsigned a2, unsigned a3,
                                         unsigned b0, unsigned b1)
{
    asm volatile("mma.sync.aligned.m16n8k8.row.col.f32.tf32.tf32.f32 "
                 "{%0,%1,%2,%3},{%4,%5,%6,%7},{%8,%9},{%0,%1,%2,%3};"
                 : "+f"(c0), "+f"(c1), "+f"(c2), "+f"(c3)
                 : "r"(a0), "r"(a1), "r"(a2), "r"(a3), "r"(b0), "r"(b1));
}

__device__ __forceinline__ void red_add_v2(float* p, float a, float b) {
    asm volatile("red.global.add.v2.f32 [%0], {%1,%2};"
                 :: "l"(p), "f"(a), "f"(b) : "memory");
}

__device__ __forceinline__ void cp_async16(void* sdst, const void* gsrc, int bytes) {
    unsigned saddr = (unsigned)__cvta_generic_to_shared(sdst);
    asm volatile("cp.async.cg.shared.global [%0], [%1], 16, %2;"
                 :: "r"(saddr), "l"(gsrc), "r"(bytes));
}
__device__ __forceinline__ void cp_commit_wait() {
    asm volatile("cp.async.commit_group;\n\tcp.async.wait_group 0;" ::: "memory");
}

// ---------------------------------------------------------------------------
// MMA over one 64-wide k-chunk in smem. As[128][ASTR] m-major, Bs[64][TN+4].
// ---------------------------------------------------------------------------
template<int TN>
__device__ __forceinline__ void mma_chunk(const unsigned (*As)[ASTR],
                                          const unsigned (*Bs)[TN + 4],
                                          int wm, int wn, int lane,
                                          float (&c)[2][TN/16][4])
{
    constexpr int NI = TN / 16;
    const int qr = lane >> 2;
    const int qc = lane & 3;
    #pragma unroll
    for (int kt = 0; kt < 8; kt++) {
        const int kb = kt * 8;
        unsigned a[2][4];
        #pragma unroll
        for (int mi = 0; mi < 2; mi++) {
            const int rb = wm + mi * 16 + qr;
            a[mi][0] = As[rb    ][kb + qc];
            a[mi][1] = As[rb + 8][kb + qc];
            a[mi][2] = As[rb    ][kb + qc + 4];
            a[mi][3] = As[rb + 8][kb + qc + 4];
        }
        unsigned b[NI][2];
        #pragma unroll
        for (int ni = 0; ni < NI; ni++) {
            const int nb = wn + ni * 8 + qr;
            b[ni][0] = Bs[kb + qc    ][nb];
            b[ni][1] = Bs[kb + qc + 4][nb];
        }
        #pragma unroll
        for (int mi = 0; mi < 2; mi++)
            #pragma unroll
            for (int ni = 0; ni < NI; ni++)
                mma_tf32(c[mi][ni][0], c[mi][ni][1], c[mi][ni][2], c[mi][ni][3],
                         a[mi][0], a[mi][1], a[mi][2], a[mi][3], b[ni][0], b[ni][1]);
    }
}

// Async-load A chunk (gathered, pre-rounded) + B chunk (pre-rounded weights).
template<int TN>
__device__ __forceinline__ void load_chunk_async(
    const float* __restrict__ X, const float* __restrict__ W,
    const int* rowsrc, int cin, int kc,
    unsigned (*As)[ASTR], unsigned (*Bs)[TN + 4], int tid)
{
    const int mrow = tid >> 4;
    const int q4   = (tid & 15) * 4;
    #pragma unroll
    for (int p = 0; p < 8; p++) {
        const int m = p * 16 + mrow;
        const int g = rowsrc[m];
        const float* src = (g >= 0) ? X + (size_t)g * cin + kc + q4 : X;
        cp_async16(&As[m][q4], src, (g >= 0) ? 16 : 0);
    }
    constexpr int N4 = TN / 4;
    #pragma unroll
    for (int l = 0; l < TN / 16; l++) {
        const int idx = tid + l * 256;
        const int n4 = idx % N4;
        const int k  = idx / N4;
        cp_async16(&Bs[k][n4 * 4], W + (size_t)(kc + k) * TN + n4 * 4, 16);
    }
    cp_commit_wait();
}

// ---------------------------------------------------------------------------
// Scatter-style tap conv.  grid = (ceil(n/128), 27)
// ---------------------------------------------------------------------------
template<int TN>
__global__ __launch_bounds__(256, 2) void conv3(
    const float* __restrict__ X, const float* __restrict__ W27,
    float* __restrict__ C, const int* __restrict__ maps,
    int Mpad, int n, int cin)
{
    constexpr int NI = TN / 16;
    __shared__ unsigned As[128][ASTR];
    __shared__ unsigned Bs[64][TN + 4];
    __shared__ int gidx[128], sidx[128];

    const int z    = blockIdx.y;
    const int Mz   = (z == 26) ? n : Mpad;
    const int row0 = blockIdx.x * 128;
    if (row0 >= Mz) return;

    const int tap  = (z == 26) ? 13 : ((z < 13) ? z : z + 1);
    const float* W = W27 + (size_t)tap * cin * TN;
    const int tid  = threadIdx.x;
    const int scrap = n;

    int myvalid = 0;
    if (tid < 128) {
        int r = row0 + tid;
        int g = -1, s = -1;
        if (r < Mz) {
            if (z == 26) { g = r; s = r; }
            else {
                g = maps[(size_t)z * Mpad + r];
                s = maps[(size_t)(26 + z) * Mpad + r];
            }
        }
        gidx[tid] = g;
        sidx[tid] = s;
        myvalid = (s >= 0 && s != scrap);
    }
    if (__syncthreads_count(myvalid) == 0) return;

    const int lane = tid & 31;
    const int warp = tid >> 5;
    const int wm = (warp & 3) * 32;
    const int wn = (warp >> 2) * (TN / 2);

    float c[2][NI][4];
    #pragma unroll
    for (int mi = 0; mi < 2; mi++)
        #pragma unroll
        for (int ni = 0; ni < NI; ni++)
            #pragma unroll
            for (int j = 0; j < 4; j++) c[mi][ni][j] = 0.f;

    for (int kc = 0; kc < cin; kc += 64) {
        if (kc) __syncthreads();
        load_chunk_async<TN>(X, W, gidx, cin, kc, As, Bs, tid);
        __syncthreads();
        mma_chunk<TN>(As, Bs, wm, wn, lane, c);
    }

    const int qr = lane >> 2, qc = lane & 3;
    #pragma unroll
    for (int mi = 0; mi < 2; mi++) {
        #pragma unroll
        for (int half = 0; half < 2; half++) {
            const int lr = wm + mi * 16 + qr + half * 8;
            const int o = sidx[lr];
            if (o < 0 || o == scrap) continue;
            float* cp = C + (size_t)o * TN + wn + qc * 2;
            #pragma unroll
            for (int ni = 0; ni < NI; ni++)
                red_add_v2(cp + ni * 8, c[mi][ni][half*2], c[mi][ni][half*2+1]);
        }
    }
}

// ---------------------------------------------------------------------------
// Batched transpose conv: T[z*n + r] = X[r] @ Wt[z].  grid = (ceil(n/128), 8)
// ---------------------------------------------------------------------------
template<int TN>
__global__ __launch_bounds__(256, 2) void tconv3(
    const float* __restrict__ X, const float* __restrict__ W8,
    float* __restrict__ T, int n, int cin)
{
    constexpr int NI = TN / 16;
    __shared__ unsigned As[128][ASTR];
    __shared__ unsigned Bs[64][TN + 4];
    __shared__ int gidx[128];

    const int z    = blockIdx.y;
    const int row0 = blockIdx.x * 128;
    if (row0 >= n) return;
    const float* W = W8 + (size_t)z * cin * TN;
    const int tid  = threadIdx.x;

    if (tid < 128) {
        int r = row0 + tid;
        gidx[tid] = (r < n) ? r : -1;
    }
    __syncthreads();

    const int lane = tid & 31;
    const int warp = tid >> 5;
    const int wm = (warp & 3) * 32;
    const int wn = (warp >> 2) * (TN / 2);

    float c[2][NI][4];
    #pragma unroll
    for (int mi = 0; mi < 2; mi++)
        #pragma unroll
        for (int ni = 0; ni < NI; ni++)
            #pragma unroll
            for (int j = 0; j < 4; j++) c[mi][ni][j] = 0.f;

    for (int kc = 0; kc < cin; kc += 64) {
        if (kc) __syncthreads();
        load_chunk_async<TN>(X, W, gidx, cin, kc, As, Bs, tid);
        __syncthreads();
        mma_chunk<TN>(As, Bs, wm, wn, lane, c);
    }

    const int qr = lane >> 2, qc = lane & 3;
    #pragma unroll
    for (int mi = 0; mi < 2; mi++) {
        #pragma unroll
        for (int half = 0; half < 2; half++) {
            const int r = row0 + wm + mi * 16 + qr + half * 8;
            if (r >= n) continue;
            float* tp = T + ((size_t)z * n + r) * TN + wn + qc * 2;
            #pragma unroll
            for (int ni = 0; ni < NI; ni++)
                *(float2*)(tp + ni * 8) = make_float2(c[mi][ni][half*2], c[mi][ni][half*2+1]);
        }
    }
}

// ---------------------------------------------------------------------------
// tf32 pre-rounding copy (f4)
// ---------------------------------------------------------------------------
__global__ void round_tf32(const float* __restrict__ src, float* __restrict__ dst,
                           long long n4)
{
    long long i = (long long)blockIdx.x * blockDim.x + threadIdx.x;
    if (i >= n4) return;
    float4 v = ((const float4*)src)[i];
    v.x = rnd_tf32(v.x); v.y = rnd_tf32(v.y);
    v.z = rnd_tf32(v.z); v.w = rnd_tf32(v.w);
    ((float4*)dst)[i] = v;
}

// ---------------------------------------------------------------------------
// BatchNorm (training-mode batch stats) + ELU
// ---------------------------------------------------------------------------
__global__ void bn_stats(const float* __restrict__ X, int n, int c,
                         float* __restrict__ stats)
{
    int ch = threadIdx.x;
    int r0 = blockIdx.x * 128;
    int rend = r0 + 128; if (rend > n) rend = n;
    float s = 0.f, sq = 0.f;
    for (int r = r0; r < rend; r++) {
        float v = X[(size_t)r * c + ch];
        s += v; sq += v * v;
    }
    atomicAdd(&stats[ch], s);
    atomicAdd(&stats[c + ch], sq);
}

template<int ROUND>
__global__ void bn_apply(const float* __restrict__ X, float* __restrict__ Y,
                         const float* __restrict__ stats,
                         const float* __restrict__ gb, long long total, int n, int c)
{
    long long i = (long long)blockIdx.x * blockDim.x + threadIdx.x;
    if (i >= total) return;
    int ch = (int)(i % c);
    float inv_n = 1.f / (float)n;
    float mu  = stats[ch] * inv_n;
    float var = stats[c + ch] * inv_n - mu * mu;
    float v = gb[ch] * (X[i] - mu) * rsqrtf(var + 1e-5f) + gb[c + ch];
    v = (v > 0.f) ? v : expm1f(v);
    Y[i] = ROUND ? rnd_tf32(v) : v;
}

// Fused: DST[idx[r]] = rnd_tf32(DST[idx[r]] + elu(bn(X[r])))
__global__ void bn_apply_add(const float* __restrict__ X, float* __restrict__ DST,
                             const int* __restrict__ idx,
                             const float* __restrict__ stats,
                             const float* __restrict__ gb, long long total, int n, int c)
{
    long long i = (long long)blockIdx.x * blockDim.x + threadIdx.x;
    if (i >= total) return;
    int r = (int)(i / c), ch = (int)(i % c);
    float inv_n = 1.f / (float)n;
    float mu  = stats[ch] * inv_n;
    float var = stats[c + ch] * inv_n - mu * mu;
    float v = gb[ch] * (X[i] - mu) * rsqrtf(var + 1e-5f) + gb[c + ch];
    v = (v > 0.f) ? v : expm1f(v);
    float* p = DST + (size_t)idx[r] * c + ch;
    *p = rnd_tf32(*p + v);
}

__global__ void scatter_copy(const float* __restrict__ src, float* __restrict__ dst,
                             const int* __restrict__ idx, long long total, int c)
{
    long long i = (long long)blockIdx.x * blockDim.x + threadIdx.x;
    if (i >= total) return;
    int r = (int)(i / c), ch = (int)(i % c);
    dst[(size_t)idx[r] * c + ch] = rnd_tf32(src[i]);
}

// ---------------------------------------------------------------------------
// Host-side orchestration
// ---------------------------------------------------------------------------
static void round_launch(const float* src, float* dst, long long nelem, cudaStream_t st)
{
    long long n4 = nelem / 4;
    round_tf32<<<(unsigned)((n4 + 255) / 256), 256, 0, st>>>(src, dst, n4);
}

static void sconv3_launch(const float* X, const float* W, const int* m,
                          int n, int Mpad, int cin, int cout, float* acc,
                          cudaStream_t st)
{
    cudaMemsetAsync(acc, 0, (size_t)(n + 1) * cout * sizeof(float), st);
    dim3 grid((n + 127) / 128, 27);
    if (cout == 128)
        conv3<128><<<grid, 256, 0, st>>>(X, W, acc, m, Mpad, n, cin);
    else
        conv3<64><<<grid, 256, 0, st>>>(X, W, acc, m, Mpad, n, cin);
}

static void tconv_launch(const float* X, const float* W8, float* T,
                         int n, int cin, int cout, cudaStream_t st)
{
    dim3 grid((n + 127) / 128, 8);
    if (cout == 128)
        tconv3<128><<<grid, 256, 0, st>>>(X, W8, T, n, cin);
    else
        tconv3<64><<<grid, 256, 0, st>>>(X, W8, T, n, cin);
}

static void bn_stats_launch(const float* X, int n, int c, float* stats, cudaStream_t st)
{
    cudaMemsetAsync(stats, 0, 2 * c * sizeof(float), st);
    bn_stats<<<(n + 127) / 128, c, 0, st>>>(X, n, c, stats);
}

template<int ROUND>
static void bn_elu_launch(const float* X, float* Y, const float* gb,
                          int n, int c, float* stats, cudaStream_t st)
{
    bn_stats_launch(X, n, c, stats, st);
    long long total = (long long)n * c;
    bn_apply<ROUND><<<(unsigned)((total + 255) / 256), 256, 0, st>>>(X, Y, stats, gb, total, n, c);
}

extern "C" void kernel_launch(void* const* d_in, const int* in_sizes, int n_in,
                              void* d_out, int out_size)
{
    const float* feats0 = (const float*)d_in[0];
    const float* feats1 = (const float*)d_in[1];
    const float* feats2 = (const float*)d_in[2];
    const float* w_out0 = (const float*)d_in[3];
    const float* w_out1 = (const float*)d_in[4];
    const float* w_out2 = (const float*)d_in[5];
    const float* wt2    = (const float*)d_in[6];
    const float* wu2    = (const float*)d_in[7];
    const float* wt1    = (const float*)d_in[8];
    const float* wu1    = (const float*)d_in[9];
    const float* bn_out0 = (const float*)d_in[10];
    const float* bn_out1 = (const float*)d_in[11];
    const float* bn_out2 = (const float*)d_in[12];
    const float* bn_up2a = (const float*)d_in[13];
    const float* bn_up2b = (const float*)d_in[14];
    const float* bn_up1a = (const float*)d_in[15];
    const float* bn_up1b = (const float*)d_in[16];
    const int* m_c2 = (const int*)d_in[19];
    const int* m_g2 = (const int*)d_in[20];
    const int* m_u1 = (const int*)d_in[21];
    const int* m_g1 = (const int*)d_in[22];
    const int* m_u0 = (const int*)d_in[23];
    const int* lat1_idx = (const int*)d_in[24];
    const int* up1_idx  = (const int*)d_in[25];
    const int* lat0_idx = (const int*)d_in[26];
    const int* up0_idx  = (const int*)d_in[27];

    const int N0 = in_sizes[0] / 64;
    const int N1 = in_sizes[1] / 128;
    const int N2 = in_sizes[2] / 256;
    const int U1 = in_sizes[17] / 128;
    const int U0 = in_sizes[18] / 64;
    const int Mc2 = in_sizes[19] / 52;
    const int Mg2 = in_sizes[20] / 52;
    const int Mu1 = in_sizes[21] / 52;
    const int Mg1 = in_sizes[22] / 52;
    const int Mu0 = in_sizes[23] / 52;
    const int G2 = 8 * N2;
    const int G1 = 8 * U1;

    float *acc2, *tg2, *accg2, *x1, *acc1, *t1, *accg1, *x0, *acc0, *stats, *wr, *f2r;
    cudaGetSymbolAddress((void**)&acc2,  g_acc2);
    cudaGetSymbolAddress((void**)&tg2,   g_tg2);
    cudaGetSymbolAddress((void**)&accg2, g_accg2);
    cudaGetSymbolAddress((void**)&x1,    g_x1);
    cudaGetSymbolAddress((void**)&acc1,  g_acc1);
    cudaGetSymbolAddress((void**)&t1,    g_t1);
    cudaGetSymbolAddress((void**)&accg1, g_accg1);
    cudaGetSymbolAddress((void**)&x0,    g_x0);
    cudaGetSymbolAddress((void**)&acc0,  g_acc0);
    cudaGetSymbolAddress((void**)&stats, g_stats);
    cudaGetSymbolAddress((void**)&wr,    g_wr);
    cudaGetSymbolAddress((void**)&f2r,   g_f2r);

    float* out0 = (float*)d_out;
    float* out1 = out0 + (size_t)U0 * 128;
    float* out2 = out1 + (size_t)U1 * 128;

    static cudaStream_t s1 = nullptr;
    static cudaEvent_t eRoot = nullptr, eF2 = nullptr, eX1 = nullptr, eEnd = nullptr;
    if (!s1) {
        cudaStreamCreateWithFlags(&s1, cudaStreamNonBlocking);
        cudaEventCreateWithFlags(&eRoot, cudaEventDisableTiming);
        cudaEventCreateWithFlags(&eF2,   cudaEventDisableTiming);
        cudaEventCreateWithFlags(&eX1,   cudaEventDisableTiming);
        cudaEventCreateWithFlags(&eEnd,  cudaEventDisableTiming);
    }
    cudaStream_t s0 = 0;

    // ---- fork ----
    cudaEventRecord(eRoot, s0);
    cudaStreamWaitEvent(s1, eRoot, 0);

    // ===== s0: round feats2 + w_out2, then out2 head =====
    round_launch(feats2, f2r, (long long)N2 * 256, s0);
    cudaEventRecord(eF2, s0);
    round_launch(w_out2, wr + O_WOUT2, 27LL * 256 * 128, s0);
    sconv3_launch(f2r, wr + O_WOUT2, m_c2, N2, Mc2, 256, 128, acc2, s0);
    bn_elu_launch<0>(acc2, out2, bn_out2, N2, 128, stats + 0*256, s0);
    round_launch(w_out1, wr + O_WOUT1, 27LL * 128 * 128, s0);

    // ===== s1: weight rounds + union bases + up path =====
    round_launch(wt2, wr + O_WT2, 8LL * 256 * 128, s1);
    round_launch(wu2, wr + O_WU2, 27LL * 128 * 128, s1);
    round_launch(wt1, wr + O_WT1, 8LL * 128 * 64, s1);
    round_launch(wu1, wr + O_WU1, 27LL * 64 * 64, s1);
    round_launch(w_out0, wr + O_WOUT0, 27LL * 64 * 128, s1);

    cudaMemsetAsync(x1, 0, (size_t)U1 * 128 * sizeof(float), s1);
    {
        long long t = (long long)N1 * 128;
        scatter_copy<<<(unsigned)((t + 255) / 256), 256, 0, s1>>>(feats1, x1, lat1_idx, t, 128);
    }
    cudaMemsetAsync(x0, 0, (size_t)U0 * 64 * sizeof(float), s1);
    {
        long long t = (long long)N0 * 64;
        scatter_copy<<<(unsigned)((t + 255) / 256), 256, 0, s1>>>(feats0, x0, lat0_idx, t, 64);
    }

    // up block 2 (needs f2r from s0)
    cudaStreamWaitEvent(s1, eF2, 0);
    tconv_launch(f2r, wr + O_WT2, tg2, N2, 256, 128, s1);
    bn_elu_launch<1>(tg2, tg2, bn_up2a, G2, 128, stats + 1*256, s1);
    sconv3_launch(tg2, wr + O_WU2, m_g2, G2, Mg2, 128, 128, accg2, s1);
    bn_stats_launch(accg2, G2, 128, stats + 2*256, s1);
    {
        long long t = (long long)G2 * 128;
        bn_apply_add<<<(unsigned)((t + 255) / 256), 256, 0, s1>>>(
            accg2, x1, up1_idx, stats + 2*256, bn_up2b, t, G2, 128);
    }
    cudaEventRecord(eX1, s1);

    // up block 1
    tconv_launch(x1, wr + O_WT1, t1, U1, 128, 64, s1);
    bn_elu_launch<1>(t1, t1, bn_up1a, G1, 64, stats + 3*256, s1);
    sconv3_launch(t1, wr + O_WU1, m_g1, G1, Mg1, 64, 64, accg1, s1);
    bn_stats_launch(accg1, G1, 64, stats + 4*256, s1);
    {
        long long t = (long long)G1 * 64;
        bn_apply_add<<<(unsigned)((t + 255) / 256), 256, 0, s1>>>(
            accg1, x0, up0_idx, stats + 4*256, bn_up1b, t, G1, 64);
    }
    // out0 head
    sconv3_launch(x0, wr + O_WOUT0, m_u0, U0, Mu0, 64, 128, acc0, s1);
    bn_elu_launch<0>(acc0, out0, bn_out0, U0, 128, stats + 5*256, s1);
    cudaEventRecord(eEnd, s1);

    // ===== s0: out1 head, overlapping up-block-1 =====
    cudaStreamWaitEvent(s0, eX1, 0);
    sconv3_launch(x1, wr + O_WOUT1, m_u1, U1, Mu1, 128, 128, acc1, s0);
    bn_elu_launch<0>(acc1, out1, bn_out1, U1, 128, stats + 6*256, s0);

    // ---- join ----
    cudaStreamWaitEvent(s0, eEnd, 0);
}

// round 10
// speedup vs baseline: 1.4654x; 1.0254x over previous
#include <cuda_runtime.h>
#include <math.h>

// ---------------------------------------------------------------------------
// Static scratch (allocation-free per harness rules)
// ---------------------------------------------------------------------------
#define N2MAX 1536
#define G2MAX (8*N2MAX)
#define U1MAX 15872
#define G1MAX (8*U1MAX)
#define U0MAX 160256

__device__ float g_acc2[(N2MAX+1)*128];
__device__ float g_tg2[(size_t)G2MAX*128];
__device__ float g_accg2[((size_t)G2MAX+1)*128];
__device__ float g_x1[(size_t)U1MAX*128];
__device__ float g_acc1[((size_t)U1MAX+1)*128];
__device__ float g_t1[(size_t)G1MAX*64];
__device__ float g_accg1[((size_t)G1MAX+1)*64];
__device__ float g_x0[(size_t)U0MAX*64];
__device__ float g_acc0[((size_t)U0MAX+1)*128];
__device__ float g_stats[8*256];

// rounded tf32-in-f32 weights, TRANSPOSED to [tap][n][k]; rounded feats2
__device__ float g_wr[2428928];
__device__ float g_f2r[(size_t)N2MAX*256];

#define O_WOUT0 0
#define O_WOUT1 221184
#define O_WOUT2 663552
#define O_WT2   1548288
#define O_WU2   1810432
#define O_WT1   2252800
#define O_WU1   2318336

#define ASTR 68   // smem row stride (words): 16B-aligned, LDSM conflict-free

__device__ __forceinline__ unsigned f2tf32(float f) {
    unsigned r;
    asm("cvt.rna.tf32.f32 %0, %1;" : "=r"(r) : "f"(f));
    return r;
}
__device__ __forceinline__ float rnd_tf32(float f) { return __uint_as_float(f2tf32(f)); }

__device__ __forceinline__ void mma_tf32(float& c0, float& c1, float& c2, float& c3,
                                         unsigned a0, unsigned a1, unsigned a2, unsigned a3,
                                         unsigned b0, unsigned b1)
{
    asm volatile("mma.sync.aligned.m16n8k8.row.col.f32.tf32.tf32.f32 "
                 "{%0,%1,%2,%3},{%4,%5,%6,%7},{%8,%9},{%0,%1,%2,%3};"
                 : "+f"(c0), "+f"(c1), "+f"(c2), "+f"(c3)
                 : "r"(a0), "r"(a1), "r"(a2), "r"(a3), "r"(b0), "r"(b1));
}

__device__ __forceinline__ void red_add_v2(float* p, float a, float b) {
    asm volatile("red.global.add.v2.f32 [%0], {%1,%2};"
                 :: "l"(p), "f"(a), "f"(b) : "memory");
}

__device__ __forceinline__ void cp_async16(void* sdst, const void* gsrc, int bytes) {
    unsigned saddr = (unsigned)__cvta_generic_to_shared(sdst);
    asm volatile("cp.async.cg.shared.global [%0], [%1], 16, %2;"
                 :: "r"(saddr), "l"(gsrc), "r"(bytes));
}
__device__ __forceinline__ void cp_commit_wait() {
    asm volatile("cp.async.commit_group;\n\tcp.async.wait_group 0;" ::: "memory");
}

// ldmatrix x4 (b16 tiles; an 8x8-f32 tile == two b16 tiles side by side)
__device__ __forceinline__ void ldsm_x4(unsigned& r0, unsigned& r1,
                                        unsigned& r2, unsigned& r3, const void* p)
{
    unsigned addr = (unsigned)__cvta_generic_to_shared(p);
    asm volatile("ldmatrix.sync.aligned.m8n8.x4.shared.b16 {%0,%1,%2,%3}, [%4];"
                 : "=r"(r0), "=r"(r1), "=r"(r2), "=r"(r3) : "r"(addr));
}

// ---------------------------------------------------------------------------
// MMA over one 64-wide k-chunk. As[128][ASTR] m-major, Bs[TN][ASTR] n-major.
// Fragments via ldmatrix.x4: tile0=rows..+7/colk, tile1=rows+8, tile2=cols+4,
// tile3=rows+8&cols+4 -> (a0,a1,a2,a3) exactly.
// ---------------------------------------------------------------------------
template<int TN>
__device__ __forceinline__ void mma_chunk(const unsigned (*As)[ASTR],
                                          const unsigned (*Bs)[ASTR],
                                          int wm, int wn, int lane,
                                          float (&c)[2][TN/16][4])
{
    constexpr int NI = TN / 16;
    const int lrow = lane & 15;
    const int lcol = (lane & 16) ? 4 : 0;
    #pragma unroll
    for (int kt = 0; kt < 8; kt++) {
        const int kb = kt * 8 + lcol;
        unsigned a[2][4];
        #pragma unroll
        for (int mi = 0; mi < 2; mi++)
            ldsm_x4(a[mi][0], a[mi][1], a[mi][2], a[mi][3],
                    &As[wm + mi * 16 + lrow][kb]);
        unsigned b[NI][2];
        #pragma unroll
        for (int nj = 0; nj < NI / 2; nj++) {
            unsigned r0, r1, r2, r3;
            ldsm_x4(r0, r1, r2, r3, &Bs[wn + nj * 16 + lrow][kb]);
            b[2*nj][0] = r0; b[2*nj+1][0] = r1;
            b[2*nj][1] = r2; b[2*nj+1][1] = r3;
        }
        #pragma unroll
        for (int mi = 0; mi < 2; mi++)
            #pragma unroll
            for (int ni = 0; ni < NI; ni++)
                mma_tf32(c[mi][ni][0], c[mi][ni][1], c[mi][ni][2], c[mi][ni][3],
                         a[mi][0], a[mi][1], a[mi][2], a[mi][3], b[ni][0], b[ni][1]);
    }
}

// Async-load A chunk (gathered rows) + B chunk (n-major transposed weights).
template<int TN>
__device__ __forceinline__ void load_chunk_async(
    const float* __restrict__ X, const float* __restrict__ Wt,
    const int* rowsrc, int cin, int kc,
    unsigned (*As)[ASTR], unsigned (*Bs)[ASTR], int tid)
{
    const int mrow = tid >> 4;
    const int q4   = (tid & 15) * 4;
    #pragma unroll
    for (int p = 0; p < 8; p++) {
        const int m = p * 16 + mrow;
        const int g = rowsrc[m];
        const float* src = (g >= 0) ? X + (size_t)g * cin + kc + q4 : X;
        cp_async16(&As[m][q4], src, (g >= 0) ? 16 : 0);
    }
    #pragma unroll
    for (int l = 0; l < TN / 16; l++) {
        const int idx = tid + l * 256;
        const int nn = idx >> 4;
        const int bq = (idx & 15) * 4;
        cp_async16(&Bs[nn][bq], Wt + (size_t)nn * cin + kc + bq, 16);
    }
    cp_commit_wait();
}

// ---------------------------------------------------------------------------
// Scatter-style tap conv.  grid = (ceil(n/128), 27). Wt27: [27][TN][cin]
// ---------------------------------------------------------------------------
template<int TN>
__global__ __launch_bounds__(256, 2) void conv3(
    const float* __restrict__ X, const float* __restrict__ Wt27,
    float* __restrict__ C, const int* __restrict__ maps,
    int Mpad, int n, int cin)
{
    constexpr int NI = TN / 16;
    __shared__ unsigned As[128][ASTR];
    __shared__ unsigned Bs[TN][ASTR];
    __shared__ int gidx[128], sidx[128];

    const int z    = blockIdx.y;
    const int Mz   = (z == 26) ? n : Mpad;
    const int row0 = blockIdx.x * 128;
    if (row0 >= Mz) return;

    const int tap  = (z == 26) ? 13 : ((z < 13) ? z : z + 1);
    const float* Wt = Wt27 + (size_t)tap * cin * TN;
    const int tid  = threadIdx.x;
    const int scrap = n;

    int myvalid = 0;
    if (tid < 128) {
        int r = row0 + tid;
        int g = -1, s = -1;
        if (r < Mz) {
            if (z == 26) { g = r; s = r; }
            else {
                g = maps[(size_t)z * Mpad + r];
                s = maps[(size_t)(26 + z) * Mpad + r];
            }
        }
        gidx[tid] = g;
        sidx[tid] = s;
        myvalid = (s >= 0 && s != scrap);
    }
    if (__syncthreads_count(myvalid) == 0) return;

    const int lane = tid & 31;
    const int warp = tid >> 5;
    const int wm = (warp & 3) * 32;
    const int wn = (warp >> 2) * (TN / 2);

    float c[2][NI][4];
    #pragma unroll
    for (int mi = 0; mi < 2; mi++)
        #pragma unroll
        for (int ni = 0; ni < NI; ni++)
            #pragma unroll
            for (int j = 0; j < 4; j++) c[mi][ni][j] = 0.f;

    for (int kc = 0; kc < cin; kc += 64) {
        if (kc) __syncthreads();
        load_chunk_async<TN>(X, Wt, gidx, cin, kc, As, Bs, tid);
        __syncthreads();
        mma_chunk<TN>(As, Bs, wm, wn, lane, c);
    }

    const int qr = lane >> 2, qc = lane & 3;
    #pragma unroll
    for (int mi = 0; mi < 2; mi++) {
        #pragma unroll
        for (int half = 0; half < 2; half++) {
            const int lr = wm + mi * 16 + qr + half * 8;
            const int o = sidx[lr];
            if (o < 0 || o == scrap) continue;
            float* cp = C + (size_t)o * TN + wn + qc * 2;
            #pragma unroll
            for (int ni = 0; ni < NI; ni++)
                red_add_v2(cp + ni * 8, c[mi][ni][half*2], c[mi][ni][half*2+1]);
        }
    }
}

// ---------------------------------------------------------------------------
// Batched transpose conv: T[z*n + r] = X[r] @ Wt[z].  grid = (ceil(n/128), 8)
// ---------------------------------------------------------------------------
template<int TN>
__global__ __launch_bounds__(256, 2) void tconv3(
    const float* __restrict__ X, const float* __restrict__ Wt8,
    float* __restrict__ T, int n, int cin)
{
    constexpr int NI = TN / 16;
    __shared__ unsigned As[128][ASTR];
    __shared__ unsigned Bs[TN][ASTR];
    __shared__ int gidx[128];

    const int z    = blockIdx.y;
    const int row0 = blockIdx.x * 128;
    if (row0 >= n) return;
    const float* Wt = Wt8 + (size_t)z * cin * TN;
    const int tid  = threadIdx.x;

    if (tid < 128) {
        int r = row0 + tid;
        gidx[tid] = (r < n) ? r : -1;
    }
    __syncthreads();

    const int lane = tid & 31;
    const int warp = tid >> 5;
    const int wm = (warp & 3) * 32;
    const int wn = (warp >> 2) * (TN / 2);

    float c[2][NI][4];
    #pragma unroll
    for (int mi = 0; mi < 2; mi++)
        #pragma unroll
        for (int ni = 0; ni < NI; ni++)
            #pragma unroll
            for (int j = 0; j < 4; j++) c[mi][ni][j] = 0.f;

    for (int kc = 0; kc < cin; kc += 64) {
        if (kc) __syncthreads();
        load_chunk_async<TN>(X, Wt, gidx, cin, kc, As, Bs, tid);
        __syncthreads();
        mma_chunk<TN>(As, Bs, wm, wn, lane, c);
    }

    const int qr = lane >> 2, qc = lane & 3;
    #pragma unroll
    for (int mi = 0; mi < 2; mi++) {
        #pragma unroll
        for (int half = 0; half < 2; half++) {
            const int r = row0 + wm + mi * 16 + qr + half * 8;
            if (r >= n) continue;
            float* tp = T + ((size_t)z * n + r) * TN + wn + qc * 2;
            #pragma unroll
            for (int ni = 0; ni < NI; ni++)
                *(float2*)(tp + ni * 8) = make_float2(c[mi][ni][half*2], c[mi][ni][half*2+1]);
        }
    }
}

// ---------------------------------------------------------------------------
// One-shot rounding kernels
// ---------------------------------------------------------------------------
__global__ void round_tf32(const float* __restrict__ src, float* __restrict__ dst,
                           long long n4)
{
    long long i = (long long)blockIdx.x * blockDim.x + threadIdx.x;
    if (i >= n4) return;
    float4 v = ((const float4*)src)[i];
    v.x = rnd_tf32(v.x); v.y = rnd_tf32(v.y);
    v.z = rnd_tf32(v.z); v.w = rnd_tf32(v.w);
    ((float4*)dst)[i] = v;
}

// src [taps][cin][cout] -> dst [taps][cout][cin], rounded (coalesced reads)
__global__ void round_transpose(const float* __restrict__ src, float* __restrict__ dst,
                                long long total, int cin, int cout)
{
    long long i = (long long)blockIdx.x * blockDim.x + threadIdx.x;
    if (i >= total) return;
    const long long per = (long long)cin * cout;
    const int t = (int)(i / per);
    const int rem = (int)(i % per);
    const int k = rem / cout, nn = rem % cout;
    dst[(long long)t * per + (long long)nn * cin + k] = rnd_tf32(src[i]);
}

// ---------------------------------------------------------------------------
// BatchNorm (training-mode batch stats) + ELU
// ---------------------------------------------------------------------------
__global__ void bn_stats(const float* __restrict__ X, int n, int c, int rpb,
                         float* __restrict__ stats)
{
    const int tpr = blockDim.x / c;           // row-groups per block
    const int ch = threadIdx.x % c;
    const int rg = threadIdx.x / c;
    const int r0 = blockIdx.x * rpb;
    int rend = r0 + rpb; if (rend > n) rend = n;
    float s = 0.f, sq = 0.f;
    for (int r = r0 + rg; r < rend; r += tpr) {
        float v = X[(size_t)r * c + ch];
        s += v; sq += v * v;
    }
    atomicAdd(&stats[ch], s);
    atomicAdd(&stats[c + ch], sq);
}

template<int ROUND>
__global__ void bn_apply(const float* __restrict__ X, float* __restrict__ Y,
                         const float* __restrict__ stats,
                         const float* __restrict__ gb, long long total, int n, int c)
{
    long long i = (long long)blockIdx.x * blockDim.x + threadIdx.x;
    if (i >= total) return;
    int ch = (int)(i % c);
    float inv_n = 1.f / (float)n;
    float mu  = stats[ch] * inv_n;
    float var = stats[c + ch] * inv_n - mu * mu;
    float v = gb[ch] * (X[i] - mu) * rsqrtf(var + 1e-5f) + gb[c + ch];
    v = (v > 0.f) ? v : expm1f(v);
    Y[i] = ROUND ? rnd_tf32(v) : v;
}

__global__ void bn_apply_add(const float* __restrict__ X, float* __restrict__ DST,
                             const int* __restrict__ idx,
                             const float* __restrict__ stats,
                             const float* __restrict__ gb, long long total, int n, int c)
{
    long long i = (long long)blockIdx.x * blockDim.x + threadIdx.x;
    if (i >= total) return;
    int r = (int)(i / c), ch = (int)(i % c);
    float inv_n = 1.f / (float)n;
    float mu  = stats[ch] * inv_n;
    float var = stats[c + ch] * inv_n - mu * mu;
    float v = gb[ch] * (X[i] - mu) * rsqrtf(var + 1e-5f) + gb[c + ch];
    v = (v > 0.f) ? v : expm1f(v);
    float* p = DST + (size_t)idx[r] * c + ch;
    *p = rnd_tf32(*p + v);
}

__global__ void scatter_copy(const float* __restrict__ src, float* __restrict__ dst,
                             const int* __restrict__ idx, long long total, int c)
{
    long long i = (long long)blockIdx.x * blockDim.x + threadIdx.x;
    if (i >= total) return;
    int r = (int)(i / c), ch = (int)(i % c);
    dst[(size_t)idx[r] * c + ch] = rnd_tf32(src[i]);
}

// ---------------------------------------------------------------------------
// Host-side orchestration
// ---------------------------------------------------------------------------
static void round_launch(const float* src, float* dst, long long nelem, cudaStream_t st)
{
    long long n4 = nelem / 4;
    round_tf32<<<(unsigned)((n4 + 255) / 256), 256, 0, st>>>(src, dst, n4);
}

static void roundT_launch(const float* src, float* dst, int taps, int cin, int cout,
                          cudaStream_t st)
{
    long long total = (long long)taps * cin * cout;
    round_transpose<<<(unsigned)((total + 255) / 256), 256, 0, st>>>(src, dst, total, cin, cout);
}

static void sconv3_launch(const float* X, const float* Wt, const int* m,
                          int n, int Mpad, int cin, int cout, float* acc,
                          cudaStream_t st)
{
    cudaMemsetAsync(acc, 0, (size_t)(n + 1) * cout * sizeof(float), st);
    dim3 grid((n + 127) / 128, 27);
    if (cout == 128)
        conv3<128><<<grid, 256, 0, st>>>(X, Wt, acc, m, Mpad, n, cin);
    else
        conv3<64><<<grid, 256, 0, st>>>(X, Wt, acc, m, Mpad, n, cin);
}

static void tconv_launch(const float* X, const float* Wt8, float* T,
                         int n, int cin, int cout, cudaStream_t st)
{
    dim3 grid((n + 127) / 128, 8);
    if (cout == 128)
        tconv3<128><<<grid, 256, 0, st>>>(X, Wt8, T, n, cin);
    else
        tconv3<64><<<grid, 256, 0, st>>>(X, Wt8, T, n, cin);
}

static void bn_stats_launch(const float* X, int n, int c, float* stats, cudaStream_t st)
{
    const int rpb = (n >= 16384) ? 128 : 32;
    bn_stats<<<(n + rpb - 1) / rpb, c * (256 / c), 0, st>>>(X, n, c, rpb, stats);
}

template<int ROUND>
static void bn_elu_launch(const float* X, float* Y, const float* gb,
                          int n, int c, float* stats, cudaStream_t st)
{
    bn_stats_launch(X, n, c, stats, st);
    long long total = (long long)n * c;
    bn_apply<ROUND><<<(unsigned)((total + 255) / 256), 256, 0, st>>>(X, Y, stats, gb, total, n, c);
}

extern "C" void kernel_launch(void* const* d_in, const int* in_sizes, int n_in,
                              void* d_out, int out_size)
{
    const float* feats0 = (const float*)d_in[0];
    const float* feats1 = (const float*)d_in[1];
    const float* feats2 = (const float*)d_in[2];
    const float* w_out0 = (const float*)d_in[3];
    const float* w_out1 = (const float*)d_in[4];
    const float* w_out2 = (const float*)d_in[5];
    const float* wt2    = (const float*)d_in[6];
    const float* wu2    = (const float*)d_in[7];
    const float* wt1    = (const float*)d_in[8];
    const float* wu1    = (const float*)d_in[9];
    const float* bn_out0 = (const float*)d_in[10];
    const float* bn_out1 = (const float*)d_in[11];
    const float* bn_out2 = (const float*)d_in[12];
    const float* bn_up2a = (const float*)d_in[13];
    const float* bn_up2b = (const float*)d_in[14];
    const float* bn_up1a = (const float*)d_in[15];
    const float* bn_up1b = (const float*)d_in[16];
    const int* m_c2 = (const int*)d_in[19];
    const int* m_g2 = (const int*)d_in[20];
    const int* m_u1 = (const int*)d_in[21];
    const int* m_g1 = (const int*)d_in[22];
    const int* m_u0 = (const int*)d_in[23];
    const int* lat1_idx = (const int*)d_in[24];
    const int* up1_idx  = (const int*)d_in[25];
    const int* lat0_idx = (const int*)d_in[26];
    const int* up0_idx  = (const int*)d_in[27];

    const int N0 = in_sizes[0] / 64;
    const int N1 = in_sizes[1] / 128;
    const int N2 = in_sizes[2] / 256;
    const int U1 = in_sizes[17] / 128;
    const int U0 = in_sizes[18] / 64;
    const int Mc2 = in_sizes[19] / 52;
    const int Mg2 = in_sizes[20] / 52;
    const int Mu1 = in_sizes[21] / 52;
    const int Mg1 = in_sizes[22] / 52;
    const int Mu0 = in_sizes[23] / 52;
    const int G2 = 8 * N2;
    const int G1 = 8 * U1;

    float *acc2, *tg2, *accg2, *x1, *acc1, *t1, *accg1, *x0, *acc0, *stats, *wr, *f2r;
    cudaGetSymbolAddress((void**)&acc2,  g_acc2);
    cudaGetSymbolAddress((void**)&tg2,   g_tg2);
    cudaGetSymbolAddress((void**)&accg2, g_accg2);
    cudaGetSymbolAddress((void**)&x1,    g_x1);
    cudaGetSymbolAddress((void**)&acc1,  g_acc1);
    cudaGetSymbolAddress((void**)&t1,    g_t1);
    cudaGetSymbolAddress((void**)&accg1, g_accg1);
    cudaGetSymbolAddress((void**)&x0,    g_x0);
    cudaGetSymbolAddress((void**)&acc0,  g_acc0);
    cudaGetSymbolAddress((void**)&stats, g_stats);
    cudaGetSymbolAddress((void**)&wr,    g_wr);
    cudaGetSymbolAddress((void**)&f2r,   g_f2r);

    float* out0 = (float*)d_out;
    float* out1 = out0 + (size_t)U0 * 128;
    float* out2 = out1 + (size_t)U1 * 128;

    static cudaStream_t s1 = nullptr;
    static cudaEvent_t eRoot = nullptr, eF2 = nullptr, eX1 = nullptr, eEnd = nullptr;
    if (!s1) {
        cudaStreamCreateWithFlags(&s1, cudaStreamNonBlocking);
        cudaEventCreateWithFlags(&eRoot, cudaEventDisableTiming);
        cudaEventCreateWithFlags(&eF2,   cudaEventDisableTiming);
        cudaEventCreateWithFlags(&eX1,   cudaEventDisableTiming);
        cudaEventCreateWithFlags(&eEnd,  cudaEventDisableTiming);
    }
    cudaStream_t s0 = 0;

    // zero ALL bn-stats slots once (replaces 7 per-BN memset nodes)
    cudaMemsetAsync(stats, 0, 8 * 256 * sizeof(float), s0);

    // ---- fork ----
    cudaEventRecord(eRoot, s0);
    cudaStreamWaitEvent(s1, eRoot, 0);

    // ===== s0: round feats2 + w_out2(T), out2 head =====
    round_launch(feats2, f2r, (long long)N2 * 256, s0);
    cudaEventRecord(eF2, s0);
    roundT_launch(w_out2, wr + O_WOUT2, 27, 256, 128, s0);
    sconv3_launch(f2r, wr + O_WOUT2, m_c2, N2, Mc2, 256, 128, acc2, s0);
    bn_elu_launch<0>(acc2, out2, bn_out2, N2, 128, stats + 0*256, s0);
    roundT_launch(w_out1, wr + O_WOUT1, 27, 128, 128, s0);

    // ===== s1: transposed weight rounds + union bases + up path =====
    roundT_launch(wt2, wr + O_WT2, 8, 256, 128, s1);
    roundT_launch(wu2, wr + O_WU2, 27, 128, 128, s1);
    roundT_launch(wt1, wr + O_WT1, 8, 128, 64, s1);
    roundT_launch(wu1, wr + O_WU1, 27, 64, 64, s1);
    roundT_launch(w_out0, wr + O_WOUT0, 27, 64, 128, s1);

    cudaMemsetAsync(x1, 0, (size_t)U1 * 128 * sizeof(float), s1);
    {
        long long t = (long long)N1 * 128;
        scatter_copy<<<(unsigned)((t + 255) / 256), 256, 0, s1>>>(feats1, x1, lat1_idx, t, 128);
    }
    cudaMemsetAsync(x0, 0, (size_t)U0 * 64 * sizeof(float), s1);
    {
        long long t = (long long)N0 * 64;
        scatter_copy<<<(unsigned)((t + 255) / 256), 256, 0, s1>>>(feats0, x0, lat0_idx, t, 64);
    }

    // up block 2 (needs f2r from s0)
    cudaStreamWaitEvent(s1, eF2, 0);
    tconv_launch(f2r, wr + O_WT2, tg2, N2, 256, 128, s1);
    bn_elu_launch<1>(tg2, tg2, bn_up2a, G2, 128, stats + 1*256, s1);
    sconv3_launch(tg2, wr + O_WU2, m_g2, G2, Mg2, 128, 128, accg2, s1);
    bn_stats_launch(accg2, G2, 128, stats + 2*256, s1);
    {
        long long t = (long long)G2 * 128;
        bn_apply_add<<<(unsigned)((t + 255) / 256), 256, 0, s1>>>(
            accg2, x1, up1_idx, stats + 2*256, bn_up2b, t, G2, 128);
    }
    cudaEventRecord(eX1, s1);

    // up block 1
    tconv_launch(x1, wr + O_WT1, t1, U1, 128, 64, s1);
    bn_elu_launch<1>(t1, t1, bn_up1a, G1, 64, stats + 3*256, s1);
    sconv3_launch(t1, wr + O_WU1, m_g1, G1, Mg1, 64, 64, accg1, s1);
    bn_stats_launch(accg1, G1, 64, stats + 4*256, s1);
    {
        long long t = (long long)G1 * 64;
        bn_apply_add<<<(unsigned)((t + 255) / 256), 256, 0, s1>>>(
            accg1, x0, up0_idx, stats + 4*256, bn_up1b, t, G1, 64);
    }
    // out0 head
    sconv3_launch(x0, wr + O_WOUT0, m_u0, U0, Mu0, 64, 128, acc0, s1);
    bn_elu_launch<0>(acc0, out0, bn_out0, U0, 128, stats + 5*256, s1);
    cudaEventRecord(eEnd, s1);

    // ===== s0: out1 head, overlapping up-block-1 =====
    cudaStreamWaitEvent(s0, eX1, 0);
    sconv3_launch(x1, wr + O_WOUT1, m_u1, U1, Mu1, 128, 128, acc1, s0);
    bn_elu_launch<0>(acc1, out1, bn_out1, U1, 128, stats + 6*256, s0);

    // ---- join ----
    cudaStreamWaitEvent(s0, eEnd, 0);
}

// round 12
// speedup vs baseline: 1.6313x; 1.1132x over previous
#include <cuda_runtime.h>
#include <cuda_fp16.h>
#include <math.h>

// ---------------------------------------------------------------------------
// Static scratch (allocation-free per harness rules)
// ---------------------------------------------------------------------------
#define N2MAX 1536
#define G2MAX (8*N2MAX)
#define U1MAX 15872
#define G1MAX (8*U1MAX)
#define U0MAX 160256

__device__ float g_acc2[(N2MAX+1)*128];
__device__ float g_accg2[((size_t)G2MAX+1)*128];
__device__ float g_acc1[((size_t)U1MAX+1)*128];
__device__ float g_accg1[((size_t)G1MAX+1)*64];
__device__ float g_acc0[((size_t)U0MAX+1)*128];
__device__ float g_stats[8*256];

// fp16 GEMM inputs
__device__ __half g_f2h[(size_t)N2MAX*256];
__device__ __half g_tg2h[(size_t)G2MAX*128];
__device__ __half g_x1h[(size_t)U1MAX*128];
__device__ __half g_t1h[(size_t)G1MAX*64];
__device__ __half g_x0h[(size_t)U0MAX*64];
// fp16 weights, n-major [tap][cout][cin]
__device__ __half g_wh[2428928];

#define O_WOUT0 0
#define O_WOUT1 221184
#define O_WOUT2 663552
#define O_WT2   1548288
#define O_WU2   1810432
#define O_WT1   2252800
#define O_WU1   2318336

#define ASTRH 72   // smem row stride in halves (144B): ldsm conflict-free, 16B-aligned

__device__ __forceinline__ unsigned smem_u32(const void* p) {
    unsigned a;
    asm("{ .reg .u64 t; cvta.to.shared.u64 t, %1; cvt.u32.u64 %0, t; }" : "=r"(a) : "l"(p));
    return a;
}
__device__ __forceinline__ void cp_async16z(void* sdst, const void* gsrc, int bytes) {
    unsigned saddr = smem_u32(sdst);
    asm volatile("cp.async.cg.shared.global [%0], [%1], 16, %2;"
                 :: "r"(saddr), "l"(gsrc), "r"(bytes));
}
__device__ __forceinline__ void cp_async16(void* sdst, const void* gsrc) {
    unsigned saddr = smem_u32(sdst);
    asm volatile("cp.async.cg.shared.global [%0], [%1], 16;" :: "r"(saddr), "l"(gsrc));
}
__device__ __forceinline__ void cp_commit_wait() {
    asm volatile("cp.async.commit_group;\n\tcp.async.wait_group 0;" ::: "memory");
}
__device__ __forceinline__ void ldsm_x4(unsigned& r0, unsigned& r1,
                                        unsigned& r2, unsigned& r3, const void* p)
{
    unsigned addr = smem_u32(p);
    asm volatile("ldmatrix.sync.aligned.m8n8.x4.shared.b16 {%0,%1,%2,%3}, [%4];"
                 : "=r"(r0), "=r"(r1), "=r"(r2), "=r"(r3) : "r"(addr));
}
__device__ __forceinline__ void mma_f16(float& c0, float& c1, float& c2, float& c3,
                                        unsigned a0, unsigned a1, unsigned a2, unsigned a3,
                                        unsigned b0, unsigned b1)
{
    asm volatile("mma.sync.aligned.m16n8k16.row.col.f32.f16.f16.f32 "
                 "{%0,%1,%2,%3},{%4,%5,%6,%7},{%8,%9},{%0,%1,%2,%3};"
                 : "+f"(c0), "+f"(c1), "+f"(c2), "+f"(c3)
                 : "r"(a0), "r"(a1), "r"(a2), "r"(a3), "r"(b0), "r"(b1));
}
__device__ __forceinline__ void red_add_v2(float* p, float a, float b) {
    asm volatile("red.global.add.v2.f32 [%0], {%1,%2};"
                 :: "l"(p), "f"(a), "f"(b) : "memory");
}

// ---------------------------------------------------------------------------
// GEMM body: 128 x TN x cin fp16, chunked by 64 k. A gathered via cp.async,
// B from n-major fp16 weights. Fragments via ldmatrix.x4 per k=16.
// ---------------------------------------------------------------------------
template<int TN>
__device__ __forceinline__ void gemm_body(
    const __half* __restrict__ X, const __half* __restrict__ Wt,
    const int* gidx, __half (*Asm)[ASTRH], __half (*Bsm)[ASTRH],
    int cin, int tid, int wm, int wn, int lane, float (&c)[2][TN/16][4])
{
    constexpr int NI = TN / 16;
    const int ar  = tid >> 1;
    const int as0 = (tid & 1) * 4;
    const int g = gidx[ar];
    const __half* asrc = X + (size_t)(g >= 0 ? g : 0) * cin;
    const int abytes = (g >= 0) ? 16 : 0;
    const int lr = lane & 15;
    const int koff = (lane >> 4) * 8;

    for (int kc = 0; kc < cin; kc += 64) {
        if (kc) __syncthreads();
        #pragma unroll
        for (int j = 0; j < 4; j++) {
            const int seg = as0 + j;
            cp_async16z(&Asm[ar][seg * 8], asrc + kc + seg * 8, abytes);
        }
        #pragma unroll
        for (int l = 0; l < TN / 32; l++) {
            const int idx = tid + l * 256;
            const int nn = idx >> 3, seg = idx & 7;
            cp_async16(&Bsm[nn][seg * 8], Wt + (size_t)nn * cin + kc + seg * 8);
        }
        cp_commit_wait();
        __syncthreads();

        #pragma unroll
        for (int kt = 0; kt < 4; kt++) {
            const int kb = kt * 16 + koff;
            unsigned a[2][4];
            #pragma unroll
            for (int mi = 0; mi < 2; mi++)
                ldsm_x4(a[mi][0], a[mi][1], a[mi][2], a[mi][3],
                        &Asm[wm + mi * 16 + lr][kb]);
            unsigned b[NI][2];
            #pragma unroll
            for (int nj = 0; nj < NI / 2; nj++) {
                unsigned r0, r1, r2, r3;
                ldsm_x4(r0, r1, r2, r3, &Bsm[wn + nj * 16 + lr][kb]);
                b[2*nj][0] = r0; b[2*nj+1][0] = r1;
                b[2*nj][1] = r2; b[2*nj+1][1] = r3;
            }
            #pragma unroll
            for (int mi = 0; mi < 2; mi++)
                #pragma unroll
                for (int ni = 0; ni < NI; ni++)
                    mma_f16(c[mi][ni][0], c[mi][ni][1], c[mi][ni][2], c[mi][ni][3],
                            a[mi][0], a[mi][1], a[mi][2], a[mi][3], b[ni][0], b[ni][1]);
        }
    }
}

// ---------------------------------------------------------------------------
// Scatter-style tap conv (fp16 HMMA + fp32 RED). grid = (ceil(n/128), 27)
// ---------------------------------------------------------------------------
template<int TN, int MAXCTA>
__global__ __launch_bounds__(256, MAXCTA) void conv3(
    const __half* __restrict__ X, const __half* __restrict__ W27,
    float* __restrict__ C, const int* __restrict__ maps,
    int Mpad, int n, int cin)
{
    constexpr int NI = TN / 16;
    __shared__ __align__(16) __half Asm[128][ASTRH];
    __shared__ __align__(16) __half Bsm[TN][ASTRH];
    __shared__ int gidx[128], sidx[128];

    const int z    = blockIdx.y;
    const int Mz   = (z == 26) ? n : Mpad;
    const int row0 = blockIdx.x * 128;
    if (row0 >= Mz) return;

    const int tap  = (z == 26) ? 13 : ((z < 13) ? z : z + 1);
    const __half* Wt = W27 + (size_t)tap * cin * TN;
    const int tid  = threadIdx.x;
    const int scrap = n;

    int myvalid = 0;
    if (tid < 128) {
        int r = row0 + tid;
        int g = -1, s = -1;
        if (r < Mz) {
            if (z == 26) { g = r; s = r; }
            else {
                g = maps[(size_t)z * Mpad + r];
                s = maps[(size_t)(26 + z) * Mpad + r];
            }
        }
        gidx[tid] = g;
        sidx[tid] = s;
        myvalid = (s >= 0 && s != scrap);
    }
    if (__syncthreads_count(myvalid) == 0) return;

    const int lane = tid & 31;
    const int warp = tid >> 5;
    const int wm = (warp & 3) * 32;
    const int wn = (warp >> 2) * (TN / 2);

    float c[2][NI][4];
    #pragma unroll
    for (int mi = 0; mi < 2; mi++)
        #pragma unroll
        for (int ni = 0; ni < NI; ni++)
            #pragma unroll
            for (int j = 0; j < 4; j++) c[mi][ni][j] = 0.f;

    gemm_body<TN>(X, Wt, gidx, Asm, Bsm, cin, tid, wm, wn, lane, c);

    const int qr = lane >> 2, qc = lane & 3;
    #pragma unroll
    for (int mi = 0; mi < 2; mi++) {
        #pragma unroll
        for (int half_ = 0; half_ < 2; half_++) {
            const int lr2 = wm + mi * 16 + qr + half_ * 8;
            const int o = sidx[lr2];
            if (o < 0 || o == scrap) continue;
            float* cp = C + (size_t)o * TN + wn + qc * 2;
            #pragma unroll
            for (int ni = 0; ni < NI; ni++)
                red_add_v2(cp + ni * 8, c[mi][ni][half_*2], c[mi][ni][half_*2+1]);
        }
    }
}

// ---------------------------------------------------------------------------
// Batched transpose conv (fp16 in, fp16 out): T[z*n + r] = X[r] @ Wt[z]
// ---------------------------------------------------------------------------
template<int TN, int MAXCTA>
__global__ __launch_bounds__(256, MAXCTA) void tconv3(
    const __half* __restrict__ X, const __half* __restrict__ W8,
    __half* __restrict__ T, int n, int cin)
{
    constexpr int NI = TN / 16;
    __shared__ __align__(16) __half Asm[128][ASTRH];
    __shared__ __align__(16) __half Bsm[TN][ASTRH];
    __shared__ int gidx[128];

    const int z    = blockIdx.y;
    const int row0 = blockIdx.x * 128;
    if (row0 >= n) return;
    const __half* Wt = W8 + (size_t)z * cin * TN;
    const int tid  = threadIdx.x;

    if (tid < 128) {
        int r = row0 + tid;
        gidx[tid] = (r < n) ? r : -1;
    }
    __syncthreads();

    const int lane = tid & 31;
    const int warp = tid >> 5;
    const int wm = (warp & 3) * 32;
    const int wn = (warp >> 2) * (TN / 2);

    float c[2][NI][4];
    #pragma unroll
    for (int mi = 0; mi < 2; mi++)
        #pragma unroll
        for (int ni = 0; ni < NI; ni++)
            #pragma unroll
            for (int j = 0; j < 4; j++) c[mi][ni][j] = 0.f;

    gemm_body<TN>(X, Wt, gidx, Asm, Bsm, cin, tid, wm, wn, lane, c);

    const int qr = lane >> 2, qc = lane & 3;
    #pragma unroll
    for (int mi = 0; mi < 2; mi++) {
        #pragma unroll
        for (int half_ = 0; half_ < 2; half_++) {
            const int r = row0 + wm + mi * 16 + qr + half_ * 8;
            if (r >= n) continue;
            __half* tp = T + ((size_t)z * n + r) * TN + wn + qc * 2;
            #pragma unroll
            for (int ni = 0; ni < NI; ni++) {
                __half2 hv = __floats2half2_rn(c[mi][ni][half_*2], c[mi][ni][half_*2+1]);
                *reinterpret_cast<__half2*>(tp + ni * 8) = hv;
            }
        }
    }
}

// ---------------------------------------------------------------------------
// One-shot converters
// ---------------------------------------------------------------------------
// weights: src fp32 [taps][cin][cout] -> dst fp16 [taps][cout][cin]
__global__ void build_wh(const float* __restrict__ src, __half* __restrict__ dst,
                         long long total, int cin, int cout)
{
    long long i = (long long)blockIdx.x * blockDim.x + threadIdx.x;
    if (i >= total) return;
    const long long per = (long long)cin * cout;
    const int t = (int)(i / per);
    const int rem = (int)(i % per);
    const int k = rem / cout, nn = rem % cout;
    dst[(long long)t * per + (long long)nn * cin + k] = __float2half(src[i]);
}

__global__ void f2h(const float* __restrict__ src, __half* __restrict__ dst, long long n)
{
    long long i = (long long)blockIdx.x * blockDim.x + threadIdx.x;
    if (i >= n) return;
    dst[i] = __float2half(src[i]);
}

// ---------------------------------------------------------------------------
// BatchNorm (training-mode batch stats) + ELU
// ---------------------------------------------------------------------------
template<typename T>
__global__ void bn_stats(const T* __restrict__ X, int n, int c, int rpb,
                         float* __restrict__ stats)
{
    const int tpr = blockDim.x / c;
    const int ch = threadIdx.x % c;
    const int rg = threadIdx.x / c;
    const int r0 = blockIdx.x * rpb;
    int rend = r0 + rpb; if (rend > n) rend = n;
    float s = 0.f, sq = 0.f;
    for (int r = r0 + rg; r < rend; r += tpr) {
        float v = (float)X[(size_t)r * c + ch];
        s += v; sq += v * v;
    }
    atomicAdd(&stats[ch], s);
    atomicAdd(&stats[c + ch], sq);
}

// final output: fp32 acc -> fp32 out
__global__ void bn_apply_ff(const float* __restrict__ X, float* __restrict__ Y,
                            const float* __restrict__ stats,
                            const float* __restrict__ gb, long long total, int n, int c)
{
    long long i = (long long)blockIdx.x * blockDim.x + threadIdx.x;
    if (i >= total) return;
    int ch = (int)(i % c);
    float inv_n = 1.f / (float)n;
    float mu  = stats[ch] * inv_n;
    float var = stats[c + ch] * inv_n - mu * mu;
    float v = gb[ch] * (X[i] - mu) * rsqrtf(var + 1e-5f) + gb[c + ch];
    Y[i] = (v > 0.f) ? v : expm1f(v);
}

// intermediate: fp16 in-place
__global__ void bn_apply_hh(const __half* __restrict__ X, __half* __restrict__ Y,
                            const float* __restrict__ stats,
                            const float* __restrict__ gb, long long total, int n, int c)
{
    long long i = (long long)blockIdx.x * blockDim.x + threadIdx.x;
    if (i >= total) return;
    int ch = (int)(i % c);
    float inv_n = 1.f / (float)n;
    float mu  = stats[ch] * inv_n;
    float var = stats[c + ch] * inv_n - mu * mu;
    float v = gb[ch] * ((float)X[i] - mu) * rsqrtf(var + 1e-5f) + gb[c + ch];
    v = (v > 0.f) ? v : expm1f(v);
    Y[i] = __float2half(v);
}

// fused: Xh[idx[r]] += elu(bn(ACC[r]))  (fp32 acc -> fp16 dest add)
__global__ void bn_apply_add(const float* __restrict__ ACC, __half* __restrict__ DST,
                             const int* __restrict__ idx,
                             const float* __restrict__ stats,
                             const float* __restrict__ gb, long long total, int n, int c)
{
    long long i = (long long)blockIdx.x * blockDim.x + threadIdx.x;
    if (i >= total) return;
    int r = (int)(i / c), ch = (int)(i % c);
    float inv_n = 1.f / (float)n;
    float mu  = stats[ch] * inv_n;
    float var = stats[c + ch] * inv_n - mu * mu;
    float v = gb[ch] * (ACC[i] - mu) * rsqrtf(var + 1e-5f) + gb[c + ch];
    v = (v > 0.f) ? v : expm1f(v);
    __half* p = DST + (size_t)idx[r] * c + ch;
    *p = __float2half((float)*p + v);
}

__global__ void scatter_copy_f2h(const float* __restrict__ src, __half* __restrict__ dst,
                                 const int* __restrict__ idx, long long total, int c)
{
    long long i = (long long)blockIdx.x * blockDim.x + threadIdx.x;
    if (i >= total) return;
    int r = (int)(i / c), ch = (int)(i % c);
    dst[(size_t)idx[r] * c + ch] = __float2half(src[i]);
}

// ---------------------------------------------------------------------------
// Host-side orchestration
// ---------------------------------------------------------------------------
static void wh_launch(const float* src, __half* dst, int taps, int cin, int cout,
                      cudaStream_t st)
{
    long long total = (long long)taps * cin * cout;
    build_wh<<<(unsigned)((total + 255) / 256), 256, 0, st>>>(src, dst, total, cin, cout);
}

static void sconv3_launch(const __half* X, const __half* W27, const int* m,
                          int n, int Mpad, int cin, int cout, float* acc,
                          cudaStream_t st)
{
    cudaMemsetAsync(acc, 0, (size_t)(n + 1) * cout * sizeof(float), st);
    dim3 grid((n + 127) / 128, 27);
    if (cout == 128)
        conv3<128, 2><<<grid, 256, 0, st>>>(X, W27, acc, m, Mpad, n, cin);
    else
        conv3<64, 3><<<grid, 256, 0, st>>>(X, W27, acc, m, Mpad, n, cin);
}

static void tconv_launch(const __half* X, const __half* W8, __half* T,
                         int n, int cin, int cout, cudaStream_t st)
{
    dim3 grid((n + 127) / 128, 8);
    if (cout == 128)
        tconv3<128, 2><<<grid, 256, 0, st>>>(X, W8, T, n, cin);
    else
        tconv3<64, 3><<<grid, 256, 0, st>>>(X, W8, T, n, cin);
}

template<typename T>
static void bn_stats_launch(const T* X, int n, int c, float* stats, cudaStream_t st)
{
    const int rpb = (n >= 16384) ? 128 : 32;
    bn_stats<T><<<(n + rpb - 1) / rpb, c * (256 / c), 0, st>>>(X, n, c, rpb, stats);
}

static void bn_elu_ff(const float* X, float* Y, const float* gb,
                      int n, int c, float* stats, cudaStream_t st)
{
    bn_stats_launch<float>(X, n, c, stats, st);
    long long total = (long long)n * c;
    bn_apply_ff<<<(unsigned)((total + 255) / 256), 256, 0, st>>>(X, Y, stats, gb, total, n, c);
}

static void bn_elu_hh(const __half* X, __half* Y, const float* gb,
                      int n, int c, float* stats, cudaStream_t st)
{
    bn_stats_launch<__half>(X, n, c, stats, st);
    long long total = (long long)n * c;
    bn_apply_hh<<<(unsigned)((total + 255) / 256), 256, 0, st>>>(X, Y, stats, gb, total, n, c);
}

extern "C" void kernel_launch(void* const* d_in, const int* in_sizes, int n_in,
                              void* d_out, int out_size)
{
    const float* feats0 = (const float*)d_in[0];
    const float* feats1 = (const float*)d_in[1];
    const float* feats2 = (const float*)d_in[2];
    const float* w_out0 = (const float*)d_in[3];
    const float* w_out1 = (const float*)d_in[4];
    const float* w_out2 = (const float*)d_in[5];
    const float* wt2    = (const float*)d_in[6];
    const float* wu2    = (const float*)d_in[7];
    const float* wt1    = (const float*)d_in[8];
    const float* wu1    = (const float*)d_in[9];
    const float* bn_out0 = (const float*)d_in[10];
    const float* bn_out1 = (const float*)d_in[11];
    const float* bn_out2 = (const float*)d_in[12];
    const float* bn_up2a = (const float*)d_in[13];
    const float* bn_up2b = (const float*)d_in[14];
    const float* bn_up1a = (const float*)d_in[15];
    const float* bn_up1b = (const float*)d_in[16];
    const int* m_c2 = (const int*)d_in[19];
    const int* m_g2 = (const int*)d_in[20];
    const int* m_u1 = (const int*)d_in[21];
    const int* m_g1 = (const int*)d_in[22];
    const int* m_u0 = (const int*)d_in[23];
    const int* lat1_idx = (const int*)d_in[24];
    const int* up1_idx  = (const int*)d_in[25];
    const int* lat0_idx = (const int*)d_in[26];
    const int* up0_idx  = (const int*)d_in[27];

    const int N0 = in_sizes[0] / 64;
    const int N1 = in_sizes[1] / 128;
    const int N2 = in_sizes[2] / 256;
    const int U1 = in_sizes[17] / 128;
    const int U0 = in_sizes[18] / 64;
    const int Mc2 = in_sizes[19] / 52;
    const int Mg2 = in_sizes[20] / 52;
    const int Mu1 = in_sizes[21] / 52;
    const int Mg1 = in_sizes[22] / 52;
    const int Mu0 = in_sizes[23] / 52;
    const int G2 = 8 * N2;
    const int G1 = 8 * U1;

    float *acc2, *accg2, *acc1, *accg1, *acc0, *stats;
    __half *f2hbuf, *tg2h, *x1h, *t1h, *x0h, *wh;
    cudaGetSymbolAddress((void**)&acc2,  g_acc2);
    cudaGetSymbolAddress((void**)&accg2, g_accg2);
    cudaGetSymbolAddress((void**)&acc1,  g_acc1);
    cudaGetSymbolAddress((void**)&accg1, g_accg1);
    cudaGetSymbolAddress((void**)&acc0,  g_acc0);
    cudaGetSymbolAddress((void**)&stats, g_stats);
    cudaGetSymbolAddress((void**)&f2hbuf, g_f2h);
    cudaGetSymbolAddress((void**)&tg2h,  g_tg2h);
    cudaGetSymbolAddress((void**)&x1h,   g_x1h);
    cudaGetSymbolAddress((void**)&t1h,   g_t1h);
    cudaGetSymbolAddress((void**)&x0h,   g_x0h);
    cudaGetSymbolAddress((void**)&wh,    g_wh);

    float* out0 = (float*)d_out;
    float* out1 = out0 + (size_t)U0 * 128;
    float* out2 = out1 + (size_t)U1 * 128;

    static cudaStream_t s1 = nullptr;
    static cudaEvent_t eRoot = nullptr, eF2 = nullptr, eX1 = nullptr, eEnd = nullptr;
    if (!s1) {
        cudaStreamCreateWithFlags(&s1, cudaStreamNonBlocking);
        cudaEventCreateWithFlags(&eRoot, cudaEventDisableTiming);
        cudaEventCreateWithFlags(&eF2,   cudaEventDisableTiming);
        cudaEventCreateWithFlags(&eX1,   cudaEventDisableTiming);
        cudaEventCreateWithFlags(&eEnd,  cudaEventDisableTiming);
    }
    cudaStream_t s0 = 0;

    // zero all bn-stats slots once
    cudaMemsetAsync(stats, 0, 8 * 256 * sizeof(float), s0);

    // ---- fork ----
    cudaEventRecord(eRoot, s0);
    cudaStreamWaitEvent(s1, eRoot, 0);

    // ===== s0: feats2 fp16 + w_out2, then out2 head =====
    {
        long long t = (long long)N2 * 256;
        f2h<<<(unsigned)((t + 255) / 256), 256, 0, s0>>>(feats2, f2hbuf, t);
    }
    cudaEventRecord(eF2, s0);
    wh_launch(w_out2, wh + O_WOUT2, 27, 256, 128, s0);
    sconv3_launch(f2hbuf, wh + O_WOUT2, m_c2, N2, Mc2, 256, 128, acc2, s0);
    bn_elu_ff(acc2, out2, bn_out2, N2, 128, stats + 0*256, s0);
    wh_launch(w_out1, wh + O_WOUT1, 27, 128, 128, s0);

    // ===== s1: weights + union bases + up path =====
    wh_launch(wt2, wh + O_WT2, 8, 256, 128, s1);
    wh_launch(wu2, wh + O_WU2, 27, 128, 128, s1);
    wh_launch(wt1, wh + O_WT1, 8, 128, 64, s1);
    wh_launch(wu1, wh + O_WU1, 27, 64, 64, s1);
    wh_launch(w_out0, wh + O_WOUT0, 27, 64, 128, s1);

    cudaMemsetAsync(x1h, 0, (size_t)U1 * 128 * sizeof(__half), s1);
    {
        long long t = (long long)N1 * 128;
        scatter_copy_f2h<<<(unsigned)((t + 255) / 256), 256, 0, s1>>>(feats1, x1h, lat1_idx, t, 128);
    }
    cudaMemsetAsync(x0h, 0, (size_t)U0 * 64 * sizeof(__half), s1);
    {
        long long t = (long long)N0 * 64;
        scatter_copy_f2h<<<(unsigned)((t + 255) / 256), 256, 0, s1>>>(feats0, x0h, lat0_idx, t, 64);
    }

    // up block 2 (needs f2hbuf from s0)
    cudaStreamWaitEvent(s1, eF2, 0);
    tconv_launch(f2hbuf, wh + O_WT2, tg2h, N2, 256, 128, s1);
    bn_elu_hh(tg2h, tg2h, bn_up2a, G2, 128, stats + 1*256, s1);
    sconv3_launch(tg2h, wh + O_WU2, m_g2, G2, Mg2, 128, 128, accg2, s1);
    bn_stats_launch<float>(accg2, G2, 128, stats + 2*256, s1);
    {
        long long t = (long long)G2 * 128;
        bn_apply_add<<<(unsigned)((t + 255) / 256), 256, 0, s1>>>(
            accg2, x1h, up1_idx, stats + 2*256, bn_up2b, t, G2, 128);
    }
    cudaEventRecord(eX1, s1);

    // up block 1
    tconv_launch(x1h, wh + O_WT1, t1h, U1, 128, 64, s1);
    bn_elu_hh(t1h, t1h, bn_up1a, G1, 64, stats + 3*256, s1);
    sconv3_launch(t1h, wh + O_WU1, m_g1, G1, Mg1, 64, 64, accg1, s1);
    bn_stats_launch<float>(accg1, G1, 64, stats + 4*256, s1);
    {
        long long t = (long long)G1 * 64;
        bn_apply_add<<<(unsigned)((t + 255) / 256), 256, 0, s1>>>(
            accg1, x0h, up0_idx, stats + 4*256, bn_up1b, t, G1, 64);
    }
    // out0 head
    sconv3_launch(x0h, wh + O_WOUT0, m_u0, U0, Mu0, 64, 128, acc0, s1);
    bn_elu_ff(acc0, out0, bn_out0, U0, 128, stats + 5*256, s1);
    cudaEventRecord(eEnd, s1);

    // ===== s0: out1 head, overlapping up-block-1 =====
    cudaStreamWaitEvent(s0, eX1, 0);
    sconv3_launch(x1h, wh + O_WOUT1, m_u1, U1, Mu1, 128, 128, acc1, s0);
    bn_elu_ff(acc1, out1, bn_out1, U1, 128, stats + 6*256, s0);

    // ---- join ----
    cudaStreamWaitEvent(s0, eEnd, 0);
}